// round 8
// baseline (speedup 1.0000x reference)
#include <cuda_runtime.h>
#include <cuda_bf16.h>
#include <cuda_fp16.h>
#include <cstdint>
#include <math.h>

#define SEQ 8192
#define DM  2048
typedef __nv_bfloat16 bf16;

// ======================= scratch (device globals) =======================
__device__ bf16   g_Xhi[(size_t)SEQ * DM], g_Xlo[(size_t)SEQ * DM];
__device__ bf16   g_Wqhi[(size_t)DM * DM], g_Wqlo[(size_t)DM * DM];
__device__ bf16   g_Wkhi[(size_t)DM * DM], g_Wklo[(size_t)DM * DM];
__device__ bf16   g_Wvhi[(size_t)DM * DM], g_Wvlo[(size_t)DM * DM];
__device__ __half g_Q16[(size_t)SEQ * DM];
__device__ __half g_Khi16[(size_t)SEQ * DM], g_Klo16[(size_t)SEQ * DM];
__device__ __half g_V16[(size_t)SEQ * DM];
__device__ float  g_S[(size_t)SEQ * SEQ];
__device__ __half g_P16[(size_t)SEQ * SEQ];

// ======================= helpers =======================
__device__ __forceinline__ uint32_t smem_u32(const void* p) {
    uint32_t a;
    asm("{ .reg .u64 t; cvta.to.shared.u64 t, %1; cvt.u32.u64 %0, t; }" : "=r"(a) : "l"(p));
    return a;
}
#define CP16(sm, gp) \
    asm volatile("cp.async.cg.shared.global [%0], [%1], 16;" :: "r"(sm), "l"(gp))
#define CP_COMMIT() asm volatile("cp.async.commit_group;")
#define CP_WAIT(n)  asm volatile("cp.async.wait_group %0;" :: "n"(n) : "memory")

__device__ __forceinline__ void ldsm_x4(uint32_t* r, uint32_t a) {
    asm volatile("ldmatrix.sync.aligned.m8n8.x4.shared.b16 {%0,%1,%2,%3}, [%4];"
        : "=r"(r[0]), "=r"(r[1]), "=r"(r[2]), "=r"(r[3]) : "r"(a));
}
__device__ __forceinline__ void ldsm_x4_t(uint32_t* r, uint32_t a) {
    asm volatile("ldmatrix.sync.aligned.m8n8.x4.trans.shared.b16 {%0,%1,%2,%3}, [%4];"
        : "=r"(r[0]), "=r"(r[1]), "=r"(r[2]), "=r"(r[3]) : "r"(a));
}
__device__ __forceinline__ void mma16816(float* c, const uint32_t* a, const uint32_t* b) {
    asm volatile("mma.sync.aligned.m16n8k16.row.col.f32.bf16.bf16.f32 "
        "{%0,%1,%2,%3}, {%4,%5,%6,%7}, {%8,%9}, {%0,%1,%2,%3};"
        : "+f"(c[0]), "+f"(c[1]), "+f"(c[2]), "+f"(c[3])
        : "r"(a[0]), "r"(a[1]), "r"(a[2]), "r"(a[3]), "r"(b[0]), "r"(b[1]));
}
__device__ __forceinline__ void mma16816h(float* c, const uint32_t* a, const uint32_t* b) {
    asm volatile("mma.sync.aligned.m16n8k16.row.col.f32.f16.f16.f32 "
        "{%0,%1,%2,%3}, {%4,%5,%6,%7}, {%8,%9}, {%0,%1,%2,%3};"
        : "+f"(c[0]), "+f"(c[1]), "+f"(c[2]), "+f"(c[3])
        : "r"(a[0]), "r"(a[1]), "r"(a[2]), "r"(a[3]), "r"(b[0]), "r"(b[1]));
}
__device__ __forceinline__ uint32_t pack_hi(float v0, float v1, uint32_t& lo) {
    bf16 h0 = __float2bfloat16(v0), h1 = __float2bfloat16(v1);
    bf16 l0 = __float2bfloat16(v0 - __bfloat162float(h0));
    bf16 l1 = __float2bfloat16(v1 - __bfloat162float(h1));
    lo = (uint32_t)__bfloat16_as_ushort(l0) | ((uint32_t)__bfloat16_as_ushort(l1) << 16);
    return (uint32_t)__bfloat16_as_ushort(h0) | ((uint32_t)__bfloat16_as_ushort(h1) << 16);
}
__device__ __forceinline__ uint32_t pack_h2(float a, float b) {
    __half2 h = __floats2half2_rn(a, b);
    return *(uint32_t*)&h;
}
__device__ __forceinline__ uint32_t pack_h2pair(float v0, float v1, uint32_t& lo) {
    __half h0 = __float2half_rn(v0), h1 = __float2half_rn(v1);
    __half l0 = __float2half_rn(v0 - __half2float(h0));
    __half l1 = __float2half_rn(v1 - __half2float(h1));
    lo = (uint32_t)__half_as_ushort(l0) | ((uint32_t)__half_as_ushort(l1) << 16);
    return (uint32_t)__half_as_ushort(h0) | ((uint32_t)__half_as_ushort(h1) << 16);
}

#define STAGE 65536
#define GSMEM (2 * STAGE)

// ======================= NT GEMM: C[M,N] = (Ahi+Alo)[M,K] @ (Bhi+Blo)[N,K]^T (bf16 3-term) ===========
// MODE 3: single fp16 out; MODE 4: fp16 hi/lo pair out.
template <int MODE>
__global__ __launch_bounds__(512, 1)
void gemm_nt_mma(const bf16* __restrict__ Ahi, const bf16* __restrict__ Alo,
                 const bf16* __restrict__ Bhi, const bf16* __restrict__ Blo,
                 __half* __restrict__ C16, __half* __restrict__ C16lo,
                 int Kdim, long ldA, long ldB, long ldC)
{
    extern __shared__ char sm[];
    const uint32_t sb = smem_u32(sm);
    const int tid = threadIdx.x, wid = tid >> 5, lane = tid & 31;
    const int wm = wid >> 2, wn = wid & 3;
    const long row0 = (long)blockIdx.y * 128, col0 = (long)blockIdx.x * 128;
    const int NC = Kdim / 64;

    uint32_t soff[2]; long aoff[2], boff[2];
#pragma unroll
    for (int j = 0; j < 2; j++) {
        int slot = tid + j * 512;
        int r = slot >> 3, c = slot & 7;
        soff[j] = (uint32_t)(r * 128 + ((c ^ (r & 7)) << 4));
        aoff[j] = (row0 + r) * ldA + c * 8;
        boff[j] = (col0 + r) * ldB + c * 8;
    }

    const int g = lane >> 3, lr = lane & 7;
    const int arow_b = wm * 32 + (g & 1) * 8 + lr;
    const int brow_b = wn * 32 + (g & 1) * 8 + lr;
    const int ch_hi = g >> 1;

    float acc[2][4][4];
#pragma unroll
    for (int i = 0; i < 2; i++)
#pragma unroll
        for (int j = 0; j < 4; j++)
#pragma unroll
            for (int q = 0; q < 4; q++) acc[i][j][q] = 0.0f;

#define NT_LOAD(buf, kb) do {                                                  \
    uint32_t s_ = sb + (uint32_t)(buf) * STAGE;                                \
    _Pragma("unroll")                                                          \
    for (int j = 0; j < 2; j++) {                                              \
        CP16(s_ +         soff[j], Ahi + aoff[j] + (kb));                      \
        CP16(s_ + 16384 + soff[j], Alo + aoff[j] + (kb));                      \
        CP16(s_ + 32768 + soff[j], Bhi + boff[j] + (kb));                      \
        CP16(s_ + 49152 + soff[j], Blo + boff[j] + (kb));                      \
    }                                                                          \
    CP_COMMIT();                                                               \
} while (0)

    NT_LOAD(0, 0);

    for (int i = 0; i < NC; i++) {
        if (i + 1 < NC) { NT_LOAD((i + 1) & 1, (long)(i + 1) * 64); CP_WAIT(1); }
        else            { CP_WAIT(0); }
        __syncthreads();
        const uint32_t As = sb + (uint32_t)(i & 1) * STAGE;
        const uint32_t Bs = As + 32768;

#pragma unroll
        for (int ks = 0; ks < 4; ks++) {
            uint32_t a[2][2][4], b[2][4][2];
#pragma unroll
            for (int comp = 0; comp < 2; comp++) {
#pragma unroll
                for (int mf = 0; mf < 2; mf++) {
                    int row = arow_b + mf * 16;
                    int ch = ks * 2 + ch_hi;
                    ldsm_x4(a[comp][mf], As + comp * 16384u + row * 128 + ((ch ^ (row & 7)) << 4));
                }
#pragma unroll
                for (int np = 0; np < 2; np++) {
                    int row = brow_b + np * 16;
                    int ch = ks * 2 + ch_hi;
                    uint32_t q[4];
                    ldsm_x4(q, Bs + comp * 16384u + row * 128 + ((ch ^ (row & 7)) << 4));
                    b[comp][np * 2][0]     = q[0]; b[comp][np * 2][1]     = q[2];
                    b[comp][np * 2 + 1][0] = q[1]; b[comp][np * 2 + 1][1] = q[3];
                }
            }
#pragma unroll
            for (int mf = 0; mf < 2; mf++)
#pragma unroll
                for (int nf = 0; nf < 4; nf++) {
                    mma16816(acc[mf][nf], a[0][mf], b[0][nf]);
                    mma16816(acc[mf][nf], a[0][mf], b[1][nf]);
                    mma16816(acc[mf][nf], a[1][mf], b[0][nf]);
                }
        }
        __syncthreads();
    }

#pragma unroll
    for (int mf = 0; mf < 2; mf++)
#pragma unroll
        for (int nf = 0; nf < 4; nf++) {
            long row = row0 + wm * 32 + mf * 16 + (lane >> 2);
            long col = col0 + wn * 32 + nf * 8 + (lane & 3) * 2;
            if (MODE == 3) {
                *(uint32_t*)(C16 + row * ldC + col)       = pack_h2(acc[mf][nf][0], acc[mf][nf][1]);
                *(uint32_t*)(C16 + (row + 8) * ldC + col) = pack_h2(acc[mf][nf][2], acc[mf][nf][3]);
            } else {  // MODE 4: fp16 hi/lo pair
                uint32_t lo0, lo1;
                uint32_t h0 = pack_h2pair(acc[mf][nf][0], acc[mf][nf][1], lo0);
                uint32_t h1 = pack_h2pair(acc[mf][nf][2], acc[mf][nf][3], lo1);
                *(uint32_t*)(C16 + row * ldC + col)         = h0;
                *(uint32_t*)(C16lo + row * ldC + col)       = lo0;
                *(uint32_t*)(C16 + (row + 8) * ldC + col)   = h1;
                *(uint32_t*)(C16lo + (row + 8) * ldC + col) = lo1;
            }
        }
#undef NT_LOAD
}

// ======================= S GEMM: C[M,N] = A16[M,K] @ (Bhi+Blo)[N,K]^T (fp16 2-term, 3-stage) =========
#define STAGE_S 49152
#define GSMEM_S (3 * STAGE_S)
__global__ __launch_bounds__(512, 1)
void gemm_s_f16(const __half* __restrict__ A, const __half* __restrict__ Bhi,
                const __half* __restrict__ Blo, float* __restrict__ Cf,
                int Kdim, long ldA, long ldB, long ldC)
{
    extern __shared__ char sm[];
    const uint32_t sb = smem_u32(sm);
    const int tid = threadIdx.x, wid = tid >> 5, lane = tid & 31;
    const int wm = wid >> 2, wn = wid & 3;
    const long row0 = (long)blockIdx.y * 128, col0 = (long)blockIdx.x * 128;
    const int NC = Kdim / 64;

    uint32_t soff[2]; long aoff[2], boff[2];
#pragma unroll
    for (int j = 0; j < 2; j++) {
        int slot = tid + j * 512;
        int r = slot >> 3, c = slot & 7;
        soff[j] = (uint32_t)(r * 128 + ((c ^ (r & 7)) << 4));
        aoff[j] = (row0 + r) * ldA + c * 8;
        boff[j] = (col0 + r) * ldB + c * 8;
    }

    const int g = lane >> 3, lr = lane & 7;
    const int arow_b = wm * 32 + (g & 1) * 8 + lr;
    const int brow_b = wn * 32 + (g & 1) * 8 + lr;
    const int ch_hi = g >> 1;

    float acc[2][4][4];
#pragma unroll
    for (int i = 0; i < 2; i++)
#pragma unroll
        for (int j = 0; j < 4; j++)
#pragma unroll
            for (int q = 0; q < 4; q++) acc[i][j][q] = 0.0f;

#define S_LOAD(buf, kb) do {                                                   \
    uint32_t s_ = sb + (uint32_t)(buf) * STAGE_S;                              \
    _Pragma("unroll")                                                          \
    for (int j = 0; j < 2; j++) {                                              \
        CP16(s_ +         soff[j], A   + aoff[j] + (kb));                      \
        CP16(s_ + 16384 + soff[j], Bhi + boff[j] + (kb));                      \
        CP16(s_ + 32768 + soff[j], Blo + boff[j] + (kb));                      \
    }                                                                          \
    CP_COMMIT();                                                               \
} while (0)

    S_LOAD(0, 0);
    S_LOAD(1, 64);

    for (int i = 0; i < NC; i++) {
        if (i + 2 < NC)      { S_LOAD((i + 2) % 3, (long)(i + 2) * 64); CP_WAIT(2); }
        else if (i + 1 < NC) { CP_WAIT(1); }
        else                 { CP_WAIT(0); }
        __syncthreads();
        const uint32_t As = sb + (uint32_t)(i % 3) * STAGE_S;
        const uint32_t Bs = As + 16384;

#pragma unroll
        for (int ks = 0; ks < 4; ks++) {
            uint32_t a[2][4], b[2][4][2];
#pragma unroll
            for (int mf = 0; mf < 2; mf++) {
                int row = arow_b + mf * 16;
                int ch = ks * 2 + ch_hi;
                ldsm_x4(a[mf], As + row * 128 + ((ch ^ (row & 7)) << 4));
            }
#pragma unroll
            for (int comp = 0; comp < 2; comp++) {
#pragma unroll
                for (int np = 0; np < 2; np++) {
                    int row = brow_b + np * 16;
                    int ch = ks * 2 + ch_hi;
                    uint32_t q[4];
                    ldsm_x4(q, Bs + comp * 16384u + row * 128 + ((ch ^ (row & 7)) << 4));
                    b[comp][np * 2][0]     = q[0]; b[comp][np * 2][1]     = q[2];
                    b[comp][np * 2 + 1][0] = q[1]; b[comp][np * 2 + 1][1] = q[3];
                }
            }
#pragma unroll
            for (int mf = 0; mf < 2; mf++)
#pragma unroll
                for (int nf = 0; nf < 4; nf++) {
                    mma16816h(acc[mf][nf], a[mf], b[0][nf]);
                    mma16816h(acc[mf][nf], a[mf], b[1][nf]);
                }
        }
        __syncthreads();
    }

#pragma unroll
    for (int mf = 0; mf < 2; mf++)
#pragma unroll
        for (int nf = 0; nf < 4; nf++) {
            long row = row0 + wm * 32 + mf * 16 + (lane >> 2);
            long col = col0 + wn * 32 + nf * 8 + (lane & 3) * 2;
            *(float2*)(Cf + row * ldC + col)       = make_float2(acc[mf][nf][0], acc[mf][nf][1]);
            *(float2*)(Cf + (row + 8) * ldC + col) = make_float2(acc[mf][nf][2], acc[mf][nf][3]);
        }
#undef S_LOAD
}

// ======================= NN GEMM (fp16 single-term): C[M,N] = A[M,K] @ B[K,N] =======================
#define STAGE_NN 32768
#define GSMEM_NN (2 * STAGE_NN)
__global__ __launch_bounds__(512, 1)
void gemm_nn_f16(const __half* __restrict__ A, const __half* __restrict__ B,
                 float* __restrict__ Cf, int Kdim, long ldA, long ldB, long ldC)
{
    extern __shared__ char sm[];
    const uint32_t sb = smem_u32(sm);
    const int tid = threadIdx.x, wid = tid >> 5, lane = tid & 31;
    const int wm = wid >> 2, wn = wid & 3;
    const long row0 = (long)blockIdx.y * 128, col0 = (long)blockIdx.x * 128;
    const int NC = Kdim / 64;

    uint32_t soffA[2], soffB[2]; long aoff[2], boff[2];
#pragma unroll
    for (int j = 0; j < 2; j++) {
        int slot = tid + j * 512;
        int ra = slot >> 3, ca = slot & 7;
        soffA[j] = (uint32_t)(ra * 128 + ((ca ^ (ra & 7)) << 4));
        aoff[j]  = (row0 + ra) * ldA + ca * 8;
        int rb = slot >> 4, cb = slot & 15;
        soffB[j] = (uint32_t)(rb * 256 + ((cb ^ (rb & 7)) << 4));
        boff[j]  = (long)rb * ldB + col0 + cb * 8;
    }

    const int g = lane >> 3, lr = lane & 7;
    const int arow_b = wm * 32 + (g & 1) * 8 + lr;
    const int krow_b = (g & 1) * 8 + lr;
    const int bch_b  = wn * 4 + (g >> 1);

    float acc[2][4][4];
#pragma unroll
    for (int i = 0; i < 2; i++)
#pragma unroll
        for (int j = 0; j < 4; j++)
#pragma unroll
            for (int q = 0; q < 4; q++) acc[i][j][q] = 0.0f;

#define NN_LOAD(buf, kb) do {                                                  \
    uint32_t s_ = sb + (uint32_t)(buf) * STAGE_NN;                             \
    long kb_ = (kb);                                                           \
    _Pragma("unroll")                                                          \
    for (int j = 0; j < 2; j++) {                                              \
        CP16(s_ +         soffA[j], A + aoff[j] + kb_);                        \
        CP16(s_ + 16384 + soffB[j], B + boff[j] + kb_ * ldB);                  \
    }                                                                          \
    CP_COMMIT();                                                               \
} while (0)

    NN_LOAD(0, 0);

    for (int i = 0; i < NC; i++) {
        if (i + 1 < NC) { NN_LOAD((i + 1) & 1, (long)(i + 1) * 64); CP_WAIT(1); }
        else            { CP_WAIT(0); }
        __syncthreads();
        const uint32_t As = sb + (uint32_t)(i & 1) * STAGE_NN;
        const uint32_t Bs = As + 16384;

#pragma unroll
        for (int ks = 0; ks < 4; ks++) {
            uint32_t a[2][4], b[4][2];
#pragma unroll
            for (int mf = 0; mf < 2; mf++) {
                int row = arow_b + mf * 16;
                int ch = ks * 2 + (g >> 1);
                ldsm_x4(a[mf], As + row * 128 + ((ch ^ (row & 7)) << 4));
            }
#pragma unroll
            for (int np = 0; np < 2; np++) {
                int krow = krow_b + ks * 16;
                int ch = bch_b + np * 2;
                uint32_t q[4];
                ldsm_x4_t(q, Bs + krow * 256 + ((ch ^ (krow & 7)) << 4));
                b[np * 2][0]     = q[0]; b[np * 2][1]     = q[1];
                b[np * 2 + 1][0] = q[2]; b[np * 2 + 1][1] = q[3];
            }
#pragma unroll
            for (int mf = 0; mf < 2; mf++)
#pragma unroll
                for (int nf = 0; nf < 4; nf++)
                    mma16816h(acc[mf][nf], a[mf], b[nf]);
        }
        __syncthreads();
    }

#pragma unroll
    for (int mf = 0; mf < 2; mf++)
#pragma unroll
        for (int nf = 0; nf < 4; nf++) {
            long row = row0 + wm * 32 + mf * 16 + (lane >> 2);
            long col = col0 + wn * 32 + nf * 8 + (lane & 3) * 2;
            *(float2*)(Cf + row * ldC + col)       = make_float2(acc[mf][nf][0], acc[mf][nf][1]);
            *(float2*)(Cf + (row + 8) * ldC + col) = make_float2(acc[mf][nf][2], acc[mf][nf][3]);
        }
#undef NN_LOAD
}

// ======================= fp32 -> bf16 hi/lo conversion =======================
__global__ __launch_bounds__(256)
void cvt_pair(const float* __restrict__ s, bf16* __restrict__ hi, bf16* __restrict__ lo, long n4)
{
    for (long i = blockIdx.x * 256 + threadIdx.x; i < n4; i += (long)gridDim.x * 256) {
        float4 v = ((const float4*)s)[i];
        uint32_t l0, l1;
        uint32_t h0 = pack_hi(v.x, v.y, l0);
        uint32_t h1 = pack_hi(v.z, v.w, l1);
        ((uint2*)hi)[i] = make_uint2(h0, h1);
        ((uint2*)lo)[i] = make_uint2(l0, l1);
    }
}

// ======================= row softmax S -> P (fp16) =======================
__global__ __launch_bounds__(256)
void softmax_f16(const float* __restrict__ S, __half* __restrict__ P)
{
    const long row = blockIdx.x;
    const float4* rp = (const float4*)(S + row * (long)SEQ);
    const int tid = threadIdx.x;
    const float scale = 0.02209708691207961f;  // 1/sqrt(2048)

    float4 v[8];
    float mx = -INFINITY;
#pragma unroll
    for (int i = 0; i < 8; i++) {
        v[i] = rp[tid + i * 256];
        mx = fmaxf(mx, fmaxf(fmaxf(v[i].x, v[i].y), fmaxf(v[i].z, v[i].w)));
    }

    __shared__ float red[256];
    red[tid] = mx;
    __syncthreads();
    for (int s = 128; s > 0; s >>= 1) {
        if (tid < s) red[tid] = fmaxf(red[tid], red[tid + s]);
        __syncthreads();
    }
    mx = red[0];
    __syncthreads();

    float sum = 0.0f;
#pragma unroll
    for (int i = 0; i < 8; i++) {
        v[i].x = __expf((v[i].x - mx) * scale);
        v[i].y = __expf((v[i].y - mx) * scale);
        v[i].z = __expf((v[i].z - mx) * scale);
        v[i].w = __expf((v[i].w - mx) * scale);
        sum += (v[i].x + v[i].y) + (v[i].z + v[i].w);
    }
    red[tid] = sum;
    __syncthreads();
    for (int s = 128; s > 0; s >>= 1) {
        if (tid < s) red[tid] += red[tid + s];
        __syncthreads();
    }
    const float inv = 1.0f / red[0];

#pragma unroll
    for (int i = 0; i < 8; i++) {
        long idx = row * (long)SEQ + (long)(tid + i * 256) * 4;
        ((uint2*)(P + idx))[0] = make_uint2(pack_h2(v[i].x * inv, v[i].y * inv),
                                            pack_h2(v[i].z * inv, v[i].w * inv));
    }
}

// ======================= launch =======================
extern "C" void kernel_launch(void* const* d_in, const int* in_sizes, int n_in,
                              void* d_out, int out_size)
{
    (void)in_sizes; (void)n_in; (void)out_size;
    const float* X  = (const float*)d_in[0];
    const float* Wq = (const float*)d_in[1];
    const float* Wk = (const float*)d_in[2];
    const float* Wv = (const float*)d_in[3];
    float* O = (float*)d_out;

    bf16 *Xhi, *Xlo, *Wqhi, *Wqlo, *Wkhi, *Wklo, *Wvhi, *Wvlo;
    __half *Q16, *Khi16, *Klo16, *V16, *P16;
    float* Smat;
    cudaGetSymbolAddress((void**)&Xhi, g_Xhi);   cudaGetSymbolAddress((void**)&Xlo, g_Xlo);
    cudaGetSymbolAddress((void**)&Wqhi, g_Wqhi); cudaGetSymbolAddress((void**)&Wqlo, g_Wqlo);
    cudaGetSymbolAddress((void**)&Wkhi, g_Wkhi); cudaGetSymbolAddress((void**)&Wklo, g_Wklo);
    cudaGetSymbolAddress((void**)&Wvhi, g_Wvhi); cudaGetSymbolAddress((void**)&Wvlo, g_Wvlo);
    cudaGetSymbolAddress((void**)&Q16, g_Q16);
    cudaGetSymbolAddress((void**)&Khi16, g_Khi16); cudaGetSymbolAddress((void**)&Klo16, g_Klo16);
    cudaGetSymbolAddress((void**)&V16, g_V16);
    cudaGetSymbolAddress((void**)&P16, g_P16);
    cudaGetSymbolAddress((void**)&Smat, g_S);

    cudaFuncSetAttribute(gemm_nt_mma<3>, cudaFuncAttributeMaxDynamicSharedMemorySize, GSMEM);
    cudaFuncSetAttribute(gemm_nt_mma<4>, cudaFuncAttributeMaxDynamicSharedMemorySize, GSMEM);
    cudaFuncSetAttribute(gemm_s_f16,     cudaFuncAttributeMaxDynamicSharedMemorySize, GSMEM_S);
    cudaFuncSetAttribute(gemm_nn_f16,    cudaFuncAttributeMaxDynamicSharedMemorySize, GSMEM_NN);

    // 1) fp32 -> bf16 hi/lo conversions
    cvt_pair<<<1024, 256>>>(X,  Xhi,  Xlo,  (long)SEQ * DM / 4);
    cvt_pair<<<512,  256>>>(Wq, Wqhi, Wqlo, (long)DM * DM / 4);
    cvt_pair<<<512,  256>>>(Wk, Wkhi, Wklo, (long)DM * DM / 4);
    cvt_pair<<<512,  256>>>(Wv, Wvhi, Wvlo, (long)DM * DM / 4);

    dim3 blk(512);
    // 2) projections (bf16 3-term): Q -> fp16 single, K -> fp16 pair, V -> fp16 single
    dim3 gp(DM / 128, SEQ / 128);
    gemm_nt_mma<3><<<gp, blk, GSMEM>>>(Xhi, Xlo, Wqhi, Wqlo, Q16, nullptr, DM, DM, DM, DM);
    gemm_nt_mma<4><<<gp, blk, GSMEM>>>(Xhi, Xlo, Wkhi, Wklo, Khi16, Klo16, DM, DM, DM, DM);
    gemm_nt_mma<3><<<gp, blk, GSMEM>>>(Xhi, Xlo, Wvhi, Wvlo, V16, nullptr, DM, DM, DM, DM);

    // 3) S = Q16 @ (Khi+Klo)^T  [SEQ,SEQ], K=DM (fp16 2-term, 3-stage)
    dim3 gs(SEQ / 128, SEQ / 128);
    gemm_s_f16<<<gs, blk, GSMEM_S>>>(Q16, Khi16, Klo16, Smat, DM, DM, DM, SEQ);

    // 4) P = softmax(S / sqrt(DM)) -> fp16
    softmax_f16<<<SEQ, 256>>>(Smat, P16);

    // 5) O = P @ V  [SEQ,DM], K=SEQ (fp16 single-term NN)
    dim3 go(DM / 128, SEQ / 128);
    gemm_nn_f16<<<go, blk, GSMEM_NN>>>(P16, V16, O, SEQ, SEQ, DM, DM);
}

// round 9
// speedup vs baseline: 1.4121x; 1.4121x over previous
#include <cuda_runtime.h>
#include <cuda_fp16.h>
#include <cstdint>
#include <math.h>

#define SEQ 8192
#define DM  2048

// ======================= scratch (device globals) =======================
__device__ __half g_X16[(size_t)SEQ * DM];
__device__ __half g_Wqh[(size_t)DM * DM], g_Wql[(size_t)DM * DM];
__device__ __half g_Wkh[(size_t)DM * DM], g_Wkl[(size_t)DM * DM];
__device__ __half g_Wvh[(size_t)DM * DM], g_Wvl[(size_t)DM * DM];
__device__ __half g_Q16[(size_t)SEQ * DM], g_K16[(size_t)SEQ * DM], g_V16[(size_t)SEQ * DM];
__device__ float  g_S[(size_t)SEQ * SEQ];
__device__ __half g_P16[(size_t)SEQ * SEQ];

// ======================= helpers =======================
__device__ __forceinline__ uint32_t smem_u32(const void* p) {
    uint32_t a;
    asm("{ .reg .u64 t; cvta.to.shared.u64 t, %1; cvt.u32.u64 %0, t; }" : "=r"(a) : "l"(p));
    return a;
}
#define CP16(sm, gp) \
    asm volatile("cp.async.cg.shared.global [%0], [%1], 16;" :: "r"(sm), "l"(gp))
#define CP_COMMIT() asm volatile("cp.async.commit_group;")
#define CP_WAIT(n)  asm volatile("cp.async.wait_group %0;" :: "n"(n) : "memory")

__device__ __forceinline__ void ldsm_x4(uint32_t* r, uint32_t a) {
    asm volatile("ldmatrix.sync.aligned.m8n8.x4.shared.b16 {%0,%1,%2,%3}, [%4];"
        : "=r"(r[0]), "=r"(r[1]), "=r"(r[2]), "=r"(r[3]) : "r"(a));
}
__device__ __forceinline__ void ldsm_x4_t(uint32_t* r, uint32_t a) {
    asm volatile("ldmatrix.sync.aligned.m8n8.x4.trans.shared.b16 {%0,%1,%2,%3}, [%4];"
        : "=r"(r[0]), "=r"(r[1]), "=r"(r[2]), "=r"(r[3]) : "r"(a));
}
__device__ __forceinline__ void mma16816h(float* c, const uint32_t* a, const uint32_t* b) {
    asm volatile("mma.sync.aligned.m16n8k16.row.col.f32.f16.f16.f32 "
        "{%0,%1,%2,%3}, {%4,%5,%6,%7}, {%8,%9}, {%0,%1,%2,%3};"
        : "+f"(c[0]), "+f"(c[1]), "+f"(c[2]), "+f"(c[3])
        : "r"(a[0]), "r"(a[1]), "r"(a[2]), "r"(a[3]), "r"(b[0]), "r"(b[1]));
}
__device__ __forceinline__ uint32_t pack_h2(float a, float b) {
    __half2 h = __floats2half2_rn(a, b);
    return *(uint32_t*)&h;
}
__device__ __forceinline__ uint32_t pack_h2pair(float v0, float v1, uint32_t& lo) {
    __half h0 = __float2half_rn(v0), h1 = __float2half_rn(v1);
    __half l0 = __float2half_rn(v0 - __half2float(h0));
    __half l1 = __float2half_rn(v1 - __half2float(h1));
    lo = (uint32_t)__half_as_ushort(l0) | ((uint32_t)__half_as_ushort(l1) << 16);
    return (uint32_t)__half_as_ushort(h0) | ((uint32_t)__half_as_ushort(h1) << 16);
}

// ======================= NT GEMM: C[M,N] = A16[M,K] @ (B0 [+ B1])[N,K]^T =======================
// NB: number of B components (1 or 2). OUT16: fp16 out (else fp32). 3-stage cp.async pipeline.
template <int NB, int OUT16>
__global__ __launch_bounds__(512, 1)
void gemm_nt_h(const __half* __restrict__ A, const __half* __restrict__ B0,
               const __half* __restrict__ B1,
               float* __restrict__ Cf, __half* __restrict__ C16,
               int Kdim, long ldA, long ldB, long ldC)
{
    constexpr uint32_t STAGE_H = 16384u * (1 + NB);
    extern __shared__ char sm[];
    const uint32_t sb = smem_u32(sm);
    const int tid = threadIdx.x, wid = tid >> 5, lane = tid & 31;
    const int wm = wid >> 2, wn = wid & 3;
    const long row0 = (long)blockIdx.y * 128, col0 = (long)blockIdx.x * 128;
    const int NC = Kdim / 64;

    uint32_t soff[2]; long aoff[2], boff[2];
#pragma unroll
    for (int j = 0; j < 2; j++) {
        int slot = tid + j * 512;
        int r = slot >> 3, c = slot & 7;
        soff[j] = (uint32_t)(r * 128 + ((c ^ (r & 7)) << 4));
        aoff[j] = (row0 + r) * ldA + c * 8;
        boff[j] = (col0 + r) * ldB + c * 8;
    }

    const int g = lane >> 3, lr = lane & 7;
    const int arow_b = wm * 32 + (g & 1) * 8 + lr;
    const int brow_b = wn * 32 + (g & 1) * 8 + lr;
    const int ch_hi = g >> 1;

    float acc[2][4][4];
#pragma unroll
    for (int i = 0; i < 2; i++)
#pragma unroll
        for (int j = 0; j < 4; j++)
#pragma unroll
            for (int q = 0; q < 4; q++) acc[i][j][q] = 0.0f;

#define H_LOAD(buf, kb) do {                                                   \
    uint32_t s_ = sb + (uint32_t)(buf) * STAGE_H;                              \
    _Pragma("unroll")                                                          \
    for (int j = 0; j < 2; j++) {                                              \
        CP16(s_ +         soff[j], A  + aoff[j] + (kb));                       \
        CP16(s_ + 16384 + soff[j], B0 + boff[j] + (kb));                       \
        if (NB == 2) CP16(s_ + 32768 + soff[j], B1 + boff[j] + (kb));          \
    }                                                                          \
    CP_COMMIT();                                                               \
} while (0)

    H_LOAD(0, 0);
    H_LOAD(1, 64);

    for (int i = 0; i < NC; i++) {
        if (i + 2 < NC)      { H_LOAD((i + 2) % 3, (long)(i + 2) * 64); CP_WAIT(2); }
        else if (i + 1 < NC) { CP_WAIT(1); }
        else                 { CP_WAIT(0); }
        __syncthreads();
        const uint32_t As = sb + (uint32_t)(i % 3) * STAGE_H;
        const uint32_t Bs = As + 16384;

#pragma unroll
        for (int ks = 0; ks < 4; ks++) {
            uint32_t a[2][4], b[NB][4][2];
#pragma unroll
            for (int mf = 0; mf < 2; mf++) {
                int row = arow_b + mf * 16;
                int ch = ks * 2 + ch_hi;
                ldsm_x4(a[mf], As + row * 128 + ((ch ^ (row & 7)) << 4));
            }
#pragma unroll
            for (int comp = 0; comp < NB; comp++) {
#pragma unroll
                for (int np = 0; np < 2; np++) {
                    int row = brow_b + np * 16;
                    int ch = ks * 2 + ch_hi;
                    uint32_t q[4];
                    ldsm_x4(q, Bs + comp * 16384u + row * 128 + ((ch ^ (row & 7)) << 4));
                    b[comp][np * 2][0]     = q[0]; b[comp][np * 2][1]     = q[2];
                    b[comp][np * 2 + 1][0] = q[1]; b[comp][np * 2 + 1][1] = q[3];
                }
            }
#pragma unroll
            for (int mf = 0; mf < 2; mf++)
#pragma unroll
                for (int nf = 0; nf < 4; nf++) {
#pragma unroll
                    for (int comp = 0; comp < NB; comp++)
                        mma16816h(acc[mf][nf], a[mf], b[comp][nf]);
                }
        }
        __syncthreads();
    }

#pragma unroll
    for (int mf = 0; mf < 2; mf++)
#pragma unroll
        for (int nf = 0; nf < 4; nf++) {
            long row = row0 + wm * 32 + mf * 16 + (lane >> 2);
            long col = col0 + wn * 32 + nf * 8 + (lane & 3) * 2;
            if (OUT16) {
                *(uint32_t*)(C16 + row * ldC + col)       = pack_h2(acc[mf][nf][0], acc[mf][nf][1]);
                *(uint32_t*)(C16 + (row + 8) * ldC + col) = pack_h2(acc[mf][nf][2], acc[mf][nf][3]);
            } else {
                *(float2*)(Cf + row * ldC + col)       = make_float2(acc[mf][nf][0], acc[mf][nf][1]);
                *(float2*)(Cf + (row + 8) * ldC + col) = make_float2(acc[mf][nf][2], acc[mf][nf][3]);
            }
        }
#undef H_LOAD
}

// ======================= NN GEMM (fp16): C[M,N] = A[M,K] @ B[K,N] =======================
#define STAGE_NN 32768
#define GSMEM_NN (2 * STAGE_NN)
__global__ __launch_bounds__(512, 1)
void gemm_nn_f16(const __half* __restrict__ A, const __half* __restrict__ B,
                 float* __restrict__ Cf, int Kdim, long ldA, long ldB, long ldC)
{
    extern __shared__ char sm[];
    const uint32_t sb = smem_u32(sm);
    const int tid = threadIdx.x, wid = tid >> 5, lane = tid & 31;
    const int wm = wid >> 2, wn = wid & 3;
    const long row0 = (long)blockIdx.y * 128, col0 = (long)blockIdx.x * 128;
    const int NC = Kdim / 64;

    uint32_t soffA[2], soffB[2]; long aoff[2], boff[2];
#pragma unroll
    for (int j = 0; j < 2; j++) {
        int slot = tid + j * 512;
        int ra = slot >> 3, ca = slot & 7;
        soffA[j] = (uint32_t)(ra * 128 + ((ca ^ (ra & 7)) << 4));
        aoff[j]  = (row0 + ra) * ldA + ca * 8;
        int rb = slot >> 4, cb = slot & 15;
        soffB[j] = (uint32_t)(rb * 256 + ((cb ^ (rb & 7)) << 4));
        boff[j]  = (long)rb * ldB + col0 + cb * 8;
    }

    const int g = lane >> 3, lr = lane & 7;
    const int arow_b = wm * 32 + (g & 1) * 8 + lr;
    const int krow_b = (g & 1) * 8 + lr;
    const int bch_b  = wn * 4 + (g >> 1);

    float acc[2][4][4];
#pragma unroll
    for (int i = 0; i < 2; i++)
#pragma unroll
        for (int j = 0; j < 4; j++)
#pragma unroll
            for (int q = 0; q < 4; q++) acc[i][j][q] = 0.0f;

#define NN_LOAD(buf, kb) do {                                                  \
    uint32_t s_ = sb + (uint32_t)(buf) * STAGE_NN;                             \
    long kb_ = (kb);                                                           \
    _Pragma("unroll")                                                          \
    for (int j = 0; j < 2; j++) {                                              \
        CP16(s_ +         soffA[j], A + aoff[j] + kb_);                        \
        CP16(s_ + 16384 + soffB[j], B + boff[j] + kb_ * ldB);                  \
    }                                                                          \
    CP_COMMIT();                                                               \
} while (0)

    NN_LOAD(0, 0);

    for (int i = 0; i < NC; i++) {
        if (i + 1 < NC) { NN_LOAD((i + 1) & 1, (long)(i + 1) * 64); CP_WAIT(1); }
        else            { CP_WAIT(0); }
        __syncthreads();
        const uint32_t As = sb + (uint32_t)(i & 1) * STAGE_NN;
        const uint32_t Bs = As + 16384;

#pragma unroll
        for (int ks = 0; ks < 4; ks++) {
            uint32_t a[2][4], b[4][2];
#pragma unroll
            for (int mf = 0; mf < 2; mf++) {
                int row = arow_b + mf * 16;
                int ch = ks * 2 + (g >> 1);
                ldsm_x4(a[mf], As + row * 128 + ((ch ^ (row & 7)) << 4));
            }
#pragma unroll
            for (int np = 0; np < 2; np++) {
                int krow = krow_b + ks * 16;
                int ch = bch_b + np * 2;
                uint32_t q[4];
                ldsm_x4_t(q, Bs + krow * 256 + ((ch ^ (krow & 7)) << 4));
                b[np * 2][0]     = q[0]; b[np * 2][1]     = q[1];
                b[np * 2 + 1][0] = q[2]; b[np * 2 + 1][1] = q[3];
            }
#pragma unroll
            for (int mf = 0; mf < 2; mf++)
#pragma unroll
                for (int nf = 0; nf < 4; nf++)
                    mma16816h(acc[mf][nf], a[mf], b[nf]);
        }
        __syncthreads();
    }

#pragma unroll
    for (int mf = 0; mf < 2; mf++)
#pragma unroll
        for (int nf = 0; nf < 4; nf++) {
            long row = row0 + wm * 32 + mf * 16 + (lane >> 2);
            long col = col0 + wn * 32 + nf * 8 + (lane & 3) * 2;
            *(float2*)(Cf + row * ldC + col)       = make_float2(acc[mf][nf][0], acc[mf][nf][1]);
            *(float2*)(Cf + (row + 8) * ldC + col) = make_float2(acc[mf][nf][2], acc[mf][nf][3]);
        }
#undef NN_LOAD
}

// ======================= conversions =======================
__global__ __launch_bounds__(256)
void cvt_h1(const float* __restrict__ s, __half* __restrict__ d, long n4)
{
    for (long i = blockIdx.x * 256 + threadIdx.x; i < n4; i += (long)gridDim.x * 256) {
        float4 v = ((const float4*)s)[i];
        ((uint2*)d)[i] = make_uint2(pack_h2(v.x, v.y), pack_h2(v.z, v.w));
    }
}
__global__ __launch_bounds__(256)
void cvt_hpair(const float* __restrict__ s, __half* __restrict__ hi, __half* __restrict__ lo, long n4)
{
    for (long i = blockIdx.x * 256 + threadIdx.x; i < n4; i += (long)gridDim.x * 256) {
        float4 v = ((const float4*)s)[i];
        uint32_t l0, l1;
        uint32_t h0 = pack_h2pair(v.x, v.y, l0);
        uint32_t h1 = pack_h2pair(v.z, v.w, l1);
        ((uint2*)hi)[i] = make_uint2(h0, h1);
        ((uint2*)lo)[i] = make_uint2(l0, l1);
    }
}

// ======================= row softmax S -> P (fp16) =======================
__global__ __launch_bounds__(256)
void softmax_f16(const float* __restrict__ S, __half* __restrict__ P)
{
    const long row = blockIdx.x;
    const float4* rp = (const float4*)(S + row * (long)SEQ);
    const int tid = threadIdx.x;
    const float scale = 0.02209708691207961f;  // 1/sqrt(2048)

    float4 v[8];
    float mx = -INFINITY;
#pragma unroll
    for (int i = 0; i < 8; i++) {
        v[i] = rp[tid + i * 256];
        mx = fmaxf(mx, fmaxf(fmaxf(v[i].x, v[i].y), fmaxf(v[i].z, v[i].w)));
    }

    __shared__ float red[256];
    red[tid] = mx;
    __syncthreads();
    for (int s = 128; s > 0; s >>= 1) {
        if (tid < s) red[tid] = fmaxf(red[tid], red[tid + s]);
        __syncthreads();
    }
    mx = red[0];
    __syncthreads();

    float sum = 0.0f;
#pragma unroll
    for (int i = 0; i < 8; i++) {
        v[i].x = __expf((v[i].x - mx) * scale);
        v[i].y = __expf((v[i].y - mx) * scale);
        v[i].z = __expf((v[i].z - mx) * scale);
        v[i].w = __expf((v[i].w - mx) * scale);
        sum += (v[i].x + v[i].y) + (v[i].z + v[i].w);
    }
    red[tid] = sum;
    __syncthreads();
    for (int s = 128; s > 0; s >>= 1) {
        if (tid < s) red[tid] += red[tid + s];
        __syncthreads();
    }
    const float inv = 1.0f / red[0];

#pragma unroll
    for (int i = 0; i < 8; i++) {
        long idx = row * (long)SEQ + (long)(tid + i * 256) * 4;
        ((uint2*)(P + idx))[0] = make_uint2(pack_h2(v[i].x * inv, v[i].y * inv),
                                            pack_h2(v[i].z * inv, v[i].w * inv));
    }
}

// ======================= launch =======================
extern "C" void kernel_launch(void* const* d_in, const int* in_sizes, int n_in,
                              void* d_out, int out_size)
{
    (void)in_sizes; (void)n_in; (void)out_size;
    const float* X  = (const float*)d_in[0];
    const float* Wq = (const float*)d_in[1];
    const float* Wk = (const float*)d_in[2];
    const float* Wv = (const float*)d_in[3];
    float* O = (float*)d_out;

    __half *X16, *Wqh, *Wql, *Wkh, *Wkl, *Wvh, *Wvl, *Q16, *K16, *V16, *P16;
    float* Smat;
    cudaGetSymbolAddress((void**)&X16, g_X16);
    cudaGetSymbolAddress((void**)&Wqh, g_Wqh); cudaGetSymbolAddress((void**)&Wql, g_Wql);
    cudaGetSymbolAddress((void**)&Wkh, g_Wkh); cudaGetSymbolAddress((void**)&Wkl, g_Wkl);
    cudaGetSymbolAddress((void**)&Wvh, g_Wvh); cudaGetSymbolAddress((void**)&Wvl, g_Wvl);
    cudaGetSymbolAddress((void**)&Q16, g_Q16);
    cudaGetSymbolAddress((void**)&K16, g_K16);
    cudaGetSymbolAddress((void**)&V16, g_V16);
    cudaGetSymbolAddress((void**)&P16, g_P16);
    cudaGetSymbolAddress((void**)&Smat, g_S);

    const int SM_P = 3 * 16384 * 3;  // NB=2 stage 48KB x3 = 144KB
    const int SM_S = 3 * 16384 * 2;  // NB=1 stage 32KB x3 = 96KB
    cudaFuncSetAttribute(gemm_nt_h<2,1>, cudaFuncAttributeMaxDynamicSharedMemorySize, SM_P);
    cudaFuncSetAttribute(gemm_nt_h<1,0>, cudaFuncAttributeMaxDynamicSharedMemorySize, SM_S);
    cudaFuncSetAttribute(gemm_nn_f16,    cudaFuncAttributeMaxDynamicSharedMemorySize, GSMEM_NN);

    // 1) conversions: X -> fp16 single; W -> fp16 hi/lo pairs
    cvt_h1<<<1024, 256>>>(X, X16, (long)SEQ * DM / 4);
    cvt_hpair<<<512, 256>>>(Wq, Wqh, Wql, (long)DM * DM / 4);
    cvt_hpair<<<512, 256>>>(Wk, Wkh, Wkl, (long)DM * DM / 4);
    cvt_hpair<<<512, 256>>>(Wv, Wvh, Wvl, (long)DM * DM / 4);

    dim3 blk(512);
    // 2) projections (fp16 2-term): Q/K/V = X16 @ (Wh+Wl)^T -> fp16
    dim3 gp(DM / 128, SEQ / 128);
    gemm_nt_h<2,1><<<gp, blk, SM_P>>>(X16, Wqh, Wql, nullptr, Q16, DM, DM, DM, DM);
    gemm_nt_h<2,1><<<gp, blk, SM_P>>>(X16, Wkh, Wkl, nullptr, K16, DM, DM, DM, DM);
    gemm_nt_h<2,1><<<gp, blk, SM_P>>>(X16, Wvh, Wvl, nullptr, V16, DM, DM, DM, DM);

    // 3) S = Q16 @ K16^T (fp16 1-term) -> fp32
    dim3 gs(SEQ / 128, SEQ / 128);
    gemm_nt_h<1,0><<<gs, blk, SM_S>>>(Q16, K16, nullptr, Smat, nullptr, DM, DM, DM, SEQ);

    // 4) P = softmax(S / sqrt(DM)) -> fp16
    softmax_f16<<<SEQ, 256>>>(Smat, P16);

    // 5) O = P @ V (fp16 NN) -> fp32
    dim3 go(DM / 128, SEQ / 128);
    gemm_nn_f16<<<go, blk, GSMEM_NN>>>(P16, V16, O, SEQ, SEQ, DM, DM);
}

// round 10
// speedup vs baseline: 1.7031x; 1.2061x over previous
#include <cuda_runtime.h>
#include <cuda_fp16.h>
#include <cstdint>
#include <math.h>

#define SEQ 8192
#define DM  2048

// ======================= scratch (device globals) =======================
__device__ __half g_X16[(size_t)SEQ * DM];
__device__ __half g_Wq16[(size_t)DM * DM], g_Wk16[(size_t)DM * DM], g_Wv16[(size_t)DM * DM];
__device__ __half g_Q16[(size_t)SEQ * DM], g_K16[(size_t)SEQ * DM], g_V16[(size_t)SEQ * DM];
__device__ float  g_S[(size_t)SEQ * SEQ];
__device__ __half g_P16[(size_t)SEQ * SEQ];

// ======================= helpers =======================
__device__ __forceinline__ uint32_t smem_u32(const void* p) {
    uint32_t a;
    asm("{ .reg .u64 t; cvta.to.shared.u64 t, %1; cvt.u32.u64 %0, t; }" : "=r"(a) : "l"(p));
    return a;
}
#define CP16(sm, gp) \
    asm volatile("cp.async.cg.shared.global [%0], [%1], 16;" :: "r"(sm), "l"(gp))
#define CP_COMMIT() asm volatile("cp.async.commit_group;")
#define CP_WAIT(n)  asm volatile("cp.async.wait_group %0;" :: "n"(n) : "memory")

__device__ __forceinline__ void ldsm_x4(uint32_t* r, uint32_t a) {
    asm volatile("ldmatrix.sync.aligned.m8n8.x4.shared.b16 {%0,%1,%2,%3}, [%4];"
        : "=r"(r[0]), "=r"(r[1]), "=r"(r[2]), "=r"(r[3]) : "r"(a));
}
__device__ __forceinline__ void ldsm_x4_t(uint32_t* r, uint32_t a) {
    asm volatile("ldmatrix.sync.aligned.m8n8.x4.trans.shared.b16 {%0,%1,%2,%3}, [%4];"
        : "=r"(r[0]), "=r"(r[1]), "=r"(r[2]), "=r"(r[3]) : "r"(a));
}
__device__ __forceinline__ void mma16816h(float* c, const uint32_t* a, const uint32_t* b) {
    asm volatile("mma.sync.aligned.m16n8k16.row.col.f32.f16.f16.f32 "
        "{%0,%1,%2,%3}, {%4,%5,%6,%7}, {%8,%9}, {%0,%1,%2,%3};"
        : "+f"(c[0]), "+f"(c[1]), "+f"(c[2]), "+f"(c[3])
        : "r"(a[0]), "r"(a[1]), "r"(a[2]), "r"(a[3]), "r"(b[0]), "r"(b[1]));
}
__device__ __forceinline__ uint32_t pack_h2(float a, float b) {
    __half2 h = __floats2half2_rn(a, b);
    return *(uint32_t*)&h;
}

// ======================= NT GEMM: C[M,N] = A16[M,K] @ B16[N,K]^T (fp16 1-term, 3-stage) ==========
// OUT16: fp16 out (else fp32).
#define STAGE_H 32768u
#define GSMEM_H (3 * STAGE_H)
template <int OUT16>
__global__ __launch_bounds__(512, 1)
void gemm_nt_h(const __half* __restrict__ A, const __half* __restrict__ B,
               float* __restrict__ Cf, __half* __restrict__ C16,
               int Kdim, long ldA, long ldB, long ldC)
{
    extern __shared__ char sm[];
    const uint32_t sb = smem_u32(sm);
    const int tid = threadIdx.x, wid = tid >> 5, lane = tid & 31;
    const int wm = wid >> 2, wn = wid & 3;
    const long row0 = (long)blockIdx.y * 128, col0 = (long)blockIdx.x * 128;
    const int NC = Kdim / 64;

    uint32_t soff[2]; long aoff[2], boff[2];
#pragma unroll
    for (int j = 0; j < 2; j++) {
        int slot = tid + j * 512;
        int r = slot >> 3, c = slot & 7;
        soff[j] = (uint32_t)(r * 128 + ((c ^ (r & 7)) << 4));
        aoff[j] = (row0 + r) * ldA + c * 8;
        boff[j] = (col0 + r) * ldB + c * 8;
    }

    const int g = lane >> 3, lr = lane & 7;
    const int arow_b = wm * 32 + (g & 1) * 8 + lr;
    const int brow_b = wn * 32 + (g & 1) * 8 + lr;
    const int ch_hi = g >> 1;

    float acc[2][4][4];
#pragma unroll
    for (int i = 0; i < 2; i++)
#pragma unroll
        for (int j = 0; j < 4; j++)
#pragma unroll
            for (int q = 0; q < 4; q++) acc[i][j][q] = 0.0f;

#define H_LOAD(buf, kb) do {                                                   \
    uint32_t s_ = sb + (uint32_t)(buf) * STAGE_H;                              \
    _Pragma("unroll")                                                          \
    for (int j = 0; j < 2; j++) {                                              \
        CP16(s_ +         soff[j], A + aoff[j] + (kb));                        \
        CP16(s_ + 16384 + soff[j], B + boff[j] + (kb));                        \
    }                                                                          \
    CP_COMMIT();                                                               \
} while (0)

    H_LOAD(0, 0);
    H_LOAD(1, 64);

    for (int i = 0; i < NC; i++) {
        if (i + 2 < NC)      { H_LOAD((i + 2) % 3, (long)(i + 2) * 64); CP_WAIT(2); }
        else if (i + 1 < NC) { CP_WAIT(1); }
        else                 { CP_WAIT(0); }
        __syncthreads();
        const uint32_t As = sb + (uint32_t)(i % 3) * STAGE_H;
        const uint32_t Bs = As + 16384;

#pragma unroll
        for (int ks = 0; ks < 4; ks++) {
            uint32_t a[2][4], b[4][2];
#pragma unroll
            for (int mf = 0; mf < 2; mf++) {
                int row = arow_b + mf * 16;
                int ch = ks * 2 + ch_hi;
                ldsm_x4(a[mf], As + row * 128 + ((ch ^ (row & 7)) << 4));
            }
#pragma unroll
            for (int np = 0; np < 2; np++) {
                int row = brow_b + np * 16;
                int ch = ks * 2 + ch_hi;
                uint32_t q[4];
                ldsm_x4(q, Bs + row * 128 + ((ch ^ (row & 7)) << 4));
                b[np * 2][0]     = q[0]; b[np * 2][1]     = q[2];
                b[np * 2 + 1][0] = q[1]; b[np * 2 + 1][1] = q[3];
            }
#pragma unroll
            for (int mf = 0; mf < 2; mf++)
#pragma unroll
                for (int nf = 0; nf < 4; nf++)
                    mma16816h(acc[mf][nf], a[mf], b[nf]);
        }
        __syncthreads();
    }

#pragma unroll
    for (int mf = 0; mf < 2; mf++)
#pragma unroll
        for (int nf = 0; nf < 4; nf++) {
            long row = row0 + wm * 32 + mf * 16 + (lane >> 2);
            long col = col0 + wn * 32 + nf * 8 + (lane & 3) * 2;
            if (OUT16) {
                *(uint32_t*)(C16 + row * ldC + col)       = pack_h2(acc[mf][nf][0], acc[mf][nf][1]);
                *(uint32_t*)(C16 + (row + 8) * ldC + col) = pack_h2(acc[mf][nf][2], acc[mf][nf][3]);
            } else {
                *(float2*)(Cf + row * ldC + col)       = make_float2(acc[mf][nf][0], acc[mf][nf][1]);
                *(float2*)(Cf + (row + 8) * ldC + col) = make_float2(acc[mf][nf][2], acc[mf][nf][3]);
            }
        }
#undef H_LOAD
}

// ======================= NN GEMM (fp16): C[M,N] = A[M,K] @ B[K,N] =======================
#define STAGE_NN 32768
#define GSMEM_NN (2 * STAGE_NN)
__global__ __launch_bounds__(512, 1)
void gemm_nn_f16(const __half* __restrict__ A, const __half* __restrict__ B,
                 float* __restrict__ Cf, int Kdim, long ldA, long ldB, long ldC)
{
    extern __shared__ char sm[];
    const uint32_t sb = smem_u32(sm);
    const int tid = threadIdx.x, wid = tid >> 5, lane = tid & 31;
    const int wm = wid >> 2, wn = wid & 3;
    const long row0 = (long)blockIdx.y * 128, col0 = (long)blockIdx.x * 128;
    const int NC = Kdim / 64;

    uint32_t soffA[2], soffB[2]; long aoff[2], boff[2];
#pragma unroll
    for (int j = 0; j < 2; j++) {
        int slot = tid + j * 512;
        int ra = slot >> 3, ca = slot & 7;
        soffA[j] = (uint32_t)(ra * 128 + ((ca ^ (ra & 7)) << 4));
        aoff[j]  = (row0 + ra) * ldA + ca * 8;
        int rb = slot >> 4, cb = slot & 15;
        soffB[j] = (uint32_t)(rb * 256 + ((cb ^ (rb & 7)) << 4));
        boff[j]  = (long)rb * ldB + col0 + cb * 8;
    }

    const int g = lane >> 3, lr = lane & 7;
    const int arow_b = wm * 32 + (g & 1) * 8 + lr;
    const int krow_b = (g & 1) * 8 + lr;
    const int bch_b  = wn * 4 + (g >> 1);

    float acc[2][4][4];
#pragma unroll
    for (int i = 0; i < 2; i++)
#pragma unroll
        for (int j = 0; j < 4; j++)
#pragma unroll
            for (int q = 0; q < 4; q++) acc[i][j][q] = 0.0f;

#define NN_LOAD(buf, kb) do {                                                  \
    uint32_t s_ = sb + (uint32_t)(buf) * STAGE_NN;                             \
    long kb_ = (kb);                                                           \
    _Pragma("unroll")                                                          \
    for (int j = 0; j < 2; j++) {                                              \
        CP16(s_ +         soffA[j], A + aoff[j] + kb_);                        \
        CP16(s_ + 16384 + soffB[j], B + boff[j] + kb_ * ldB);                  \
    }                                                                          \
    CP_COMMIT();                                                               \
} while (0)

    NN_LOAD(0, 0);

    for (int i = 0; i < NC; i++) {
        if (i + 1 < NC) { NN_LOAD((i + 1) & 1, (long)(i + 1) * 64); CP_WAIT(1); }
        else            { CP_WAIT(0); }
        __syncthreads();
        const uint32_t As = sb + (uint32_t)(i & 1) * STAGE_NN;
        const uint32_t Bs = As + 16384;

#pragma unroll
        for (int ks = 0; ks < 4; ks++) {
            uint32_t a[2][4], b[4][2];
#pragma unroll
            for (int mf = 0; mf < 2; mf++) {
                int row = arow_b + mf * 16;
                int ch = ks * 2 + (g >> 1);
                ldsm_x4(a[mf], As + row * 128 + ((ch ^ (row & 7)) << 4));
            }
#pragma unroll
            for (int np = 0; np < 2; np++) {
                int krow = krow_b + ks * 16;
                int ch = bch_b + np * 2;
                uint32_t q[4];
                ldsm_x4_t(q, Bs + krow * 256 + ((ch ^ (krow & 7)) << 4));
                b[np * 2][0]     = q[0]; b[np * 2][1]     = q[1];
                b[np * 2 + 1][0] = q[2]; b[np * 2 + 1][1] = q[3];
            }
#pragma unroll
            for (int mf = 0; mf < 2; mf++)
#pragma unroll
                for (int nf = 0; nf < 4; nf++)
                    mma16816h(acc[mf][nf], a[mf], b[nf]);
        }
        __syncthreads();
    }

#pragma unroll
    for (int mf = 0; mf < 2; mf++)
#pragma unroll
        for (int nf = 0; nf < 4; nf++) {
            long row = row0 + wm * 32 + mf * 16 + (lane >> 2);
            long col = col0 + wn * 32 + nf * 8 + (lane & 3) * 2;
            *(float2*)(Cf + row * ldC + col)       = make_float2(acc[mf][nf][0], acc[mf][nf][1]);
            *(float2*)(Cf + (row + 8) * ldC + col) = make_float2(acc[mf][nf][2], acc[mf][nf][3]);
        }
#undef NN_LOAD
}

// ======================= fp32 -> fp16 conversion =======================
__global__ __launch_bounds__(256)
void cvt_h1(const float* __restrict__ s, __half* __restrict__ d, long n4)
{
    for (long i = blockIdx.x * 256 + threadIdx.x; i < n4; i += (long)gridDim.x * 256) {
        float4 v = ((const float4*)s)[i];
        ((uint2*)d)[i] = make_uint2(pack_h2(v.x, v.y), pack_h2(v.z, v.w));
    }
}

// ======================= row softmax S -> P (fp16) =======================
__global__ __launch_bounds__(256)
void softmax_f16(const float* __restrict__ S, __half* __restrict__ P)
{
    const long row = blockIdx.x;
    const float4* rp = (const float4*)(S + row * (long)SEQ);
    const int tid = threadIdx.x;
    const float scale = 0.02209708691207961f;  // 1/sqrt(2048)

    float4 v[8];
    float mx = -INFINITY;
#pragma unroll
    for (int i = 0; i < 8; i++) {
        v[i] = rp[tid + i * 256];
        mx = fmaxf(mx, fmaxf(fmaxf(v[i].x, v[i].y), fmaxf(v[i].z, v[i].w)));
    }

    __shared__ float red[256];
    red[tid] = mx;
    __syncthreads();
    for (int s = 128; s > 0; s >>= 1) {
        if (tid < s) red[tid] = fmaxf(red[tid], red[tid + s]);
        __syncthreads();
    }
    mx = red[0];
    __syncthreads();

    float sum = 0.0f;
#pragma unroll
    for (int i = 0; i < 8; i++) {
        v[i].x = __expf((v[i].x - mx) * scale);
        v[i].y = __expf((v[i].y - mx) * scale);
        v[i].z = __expf((v[i].z - mx) * scale);
        v[i].w = __expf((v[i].w - mx) * scale);
        sum += (v[i].x + v[i].y) + (v[i].z + v[i].w);
    }
    red[tid] = sum;
    __syncthreads();
    for (int s = 128; s > 0; s >>= 1) {
        if (tid < s) red[tid] += red[tid + s];
        __syncthreads();
    }
    const float inv = 1.0f / red[0];

#pragma unroll
    for (int i = 0; i < 8; i++) {
        long idx = row * (long)SEQ + (long)(tid + i * 256) * 4;
        ((uint2*)(P + idx))[0] = make_uint2(pack_h2(v[i].x * inv, v[i].y * inv),
                                            pack_h2(v[i].z * inv, v[i].w * inv));
    }
}

// ======================= launch =======================
extern "C" void kernel_launch(void* const* d_in, const int* in_sizes, int n_in,
                              void* d_out, int out_size)
{
    (void)in_sizes; (void)n_in; (void)out_size;
    const float* X  = (const float*)d_in[0];
    const float* Wq = (const float*)d_in[1];
    const float* Wk = (const float*)d_in[2];
    const float* Wv = (const float*)d_in[3];
    float* O = (float*)d_out;

    __half *X16, *Wq16, *Wk16, *Wv16, *Q16, *K16, *V16, *P16;
    float* Smat;
    cudaGetSymbolAddress((void**)&X16, g_X16);
    cudaGetSymbolAddress((void**)&Wq16, g_Wq16);
    cudaGetSymbolAddress((void**)&Wk16, g_Wk16);
    cudaGetSymbolAddress((void**)&Wv16, g_Wv16);
    cudaGetSymbolAddress((void**)&Q16, g_Q16);
    cudaGetSymbolAddress((void**)&K16, g_K16);
    cudaGetSymbolAddress((void**)&V16, g_V16);
    cudaGetSymbolAddress((void**)&P16, g_P16);
    cudaGetSymbolAddress((void**)&Smat, g_S);

    cudaFuncSetAttribute(gemm_nt_h<1>, cudaFuncAttributeMaxDynamicSharedMemorySize, GSMEM_H);
    cudaFuncSetAttribute(gemm_nt_h<0>, cudaFuncAttributeMaxDynamicSharedMemorySize, GSMEM_H);
    cudaFuncSetAttribute(gemm_nn_f16,  cudaFuncAttributeMaxDynamicSharedMemorySize, GSMEM_NN);

    // 1) conversions: everything -> single fp16
    cvt_h1<<<2048, 256>>>(X,  X16,  (long)SEQ * DM / 4);
    cvt_h1<<<1024, 256>>>(Wq, Wq16, (long)DM * DM / 4);
    cvt_h1<<<1024, 256>>>(Wk, Wk16, (long)DM * DM / 4);
    cvt_h1<<<1024, 256>>>(Wv, Wv16, (long)DM * DM / 4);

    dim3 blk(512);
    // 2) projections (fp16 1-term): Q/K/V = X16 @ W16^T -> fp16
    dim3 gp(DM / 128, SEQ / 128);
    gemm_nt_h<1><<<gp, blk, GSMEM_H>>>(X16, Wq16, nullptr, Q16, DM, DM, DM, DM);
    gemm_nt_h<1><<<gp, blk, GSMEM_H>>>(X16, Wk16, nullptr, K16, DM, DM, DM, DM);
    gemm_nt_h<1><<<gp, blk, GSMEM_H>>>(X16, Wv16, nullptr, V16, DM, DM, DM, DM);

    // 3) S = Q16 @ K16^T (fp16 1-term) -> fp32
    dim3 gs(SEQ / 128, SEQ / 128);
    gemm_nt_h<0><<<gs, blk, GSMEM_H>>>(Q16, K16, Smat, nullptr, DM, DM, DM, SEQ);

    // 4) P = softmax(S / sqrt(DM)) -> fp16
    softmax_f16<<<SEQ, 256>>>(Smat, P16);

    // 5) O = P @ V (fp16 NN) -> fp32
    dim3 go(DM / 128, SEQ / 128);
    gemm_nn_f16<<<go, blk, GSMEM_NN>>>(P16, V16, O, SEQ, SEQ, DM, DM);
}

// round 11
// speedup vs baseline: 1.8567x; 1.0902x over previous
#include <cuda_runtime.h>
#include <cuda_fp16.h>
#include <cstdint>
#include <math.h>

#define SEQ 8192
#define DM  2048

// ======================= scratch (device globals) =======================
__device__ __half g_X16[(size_t)SEQ * DM];
__device__ __half g_Wq16[(size_t)DM * DM], g_Wk16[(size_t)DM * DM], g_Wv16[(size_t)DM * DM];
__device__ __half g_Q16[(size_t)SEQ * DM], g_K16[(size_t)SEQ * DM], g_V16[(size_t)SEQ * DM];
__device__ float  g_S[(size_t)SEQ * SEQ];
__device__ __half g_P16[(size_t)SEQ * SEQ];

// ======================= helpers =======================
__device__ __forceinline__ uint32_t smem_u32(const void* p) {
    uint32_t a;
    asm("{ .reg .u64 t; cvta.to.shared.u64 t, %1; cvt.u32.u64 %0, t; }" : "=r"(a) : "l"(p));
    return a;
}
#define CP16(sm, gp) \
    asm volatile("cp.async.cg.shared.global [%0], [%1], 16;" :: "r"(sm), "l"(gp))
#define CP_COMMIT() asm volatile("cp.async.commit_group;")
#define CP_WAIT(n)  asm volatile("cp.async.wait_group %0;" :: "n"(n) : "memory")

__device__ __forceinline__ void ldsm_x4(uint32_t* r, uint32_t a) {
    asm volatile("ldmatrix.sync.aligned.m8n8.x4.shared.b16 {%0,%1,%2,%3}, [%4];"
        : "=r"(r[0]), "=r"(r[1]), "=r"(r[2]), "=r"(r[3]) : "r"(a));
}
__device__ __forceinline__ void ldsm_x4_t(uint32_t* r, uint32_t a) {
    asm volatile("ldmatrix.sync.aligned.m8n8.x4.trans.shared.b16 {%0,%1,%2,%3}, [%4];"
        : "=r"(r[0]), "=r"(r[1]), "=r"(r[2]), "=r"(r[3]) : "r"(a));
}
__device__ __forceinline__ void mma16816h(float* c, const uint32_t* a, const uint32_t* b) {
    asm volatile("mma.sync.aligned.m16n8k16.row.col.f32.f16.f16.f32 "
        "{%0,%1,%2,%3}, {%4,%5,%6,%7}, {%8,%9}, {%0,%1,%2,%3};"
        : "+f"(c[0]), "+f"(c[1]), "+f"(c[2]), "+f"(c[3])
        : "r"(a[0]), "r"(a[1]), "r"(a[2]), "r"(a[3]), "r"(b[0]), "r"(b[1]));
}
__device__ __forceinline__ uint32_t pack_h2(float a, float b) {
    __half2 h = __floats2half2_rn(a, b);
    return *(uint32_t*)&h;
}

// ======================= NT GEMM: C[M,N] = A16[M,K] @ B16[N,K]^T (fp16, 4-stage, 1 sync/chunk) ====
// OUT16: fp16 out (else fp32).
#define STAGE_H 32768u
#define GSMEM_H (4 * STAGE_H)
template <int OUT16>
__global__ __launch_bounds__(512, 1)
void gemm_nt_h(const __half* __restrict__ A, const __half* __restrict__ B,
               float* __restrict__ Cf, __half* __restrict__ C16,
               int Kdim, long ldA, long ldB, long ldC)
{
    extern __shared__ char sm[];
    const uint32_t sb = smem_u32(sm);
    const int tid = threadIdx.x, wid = tid >> 5, lane = tid & 31;
    const int wm = wid >> 2, wn = wid & 3;
    const long row0 = (long)blockIdx.y * 128, col0 = (long)blockIdx.x * 128;
    const int NC = Kdim / 64;

    uint32_t soff[2]; long aoff[2], boff[2];
#pragma unroll
    for (int j = 0; j < 2; j++) {
        int slot = tid + j * 512;
        int r = slot >> 3, c = slot & 7;
        soff[j] = (uint32_t)(r * 128 + ((c ^ (r & 7)) << 4));
        aoff[j] = (row0 + r) * ldA + c * 8;
        boff[j] = (col0 + r) * ldB + c * 8;
    }

    const int g = lane >> 3, lr = lane & 7;
    const int arow_b = wm * 32 + (g & 1) * 8 + lr;
    const int brow_b = wn * 32 + (g & 1) * 8 + lr;
    const int ch_hi = g >> 1;

    float acc[2][4][4];
#pragma unroll
    for (int i = 0; i < 2; i++)
#pragma unroll
        for (int j = 0; j < 4; j++)
#pragma unroll
            for (int q = 0; q < 4; q++) acc[i][j][q] = 0.0f;

#define H_LOAD(buf, kb) do {                                                   \
    uint32_t s_ = sb + (uint32_t)(buf) * STAGE_H;                              \
    _Pragma("unroll")                                                          \
    for (int j = 0; j < 2; j++) {                                              \
        CP16(s_ +         soff[j], A + aoff[j] + (kb));                        \
        CP16(s_ + 16384 + soff[j], B + boff[j] + (kb));                        \
    }                                                                          \
    CP_COMMIT();                                                               \
} while (0)

    H_LOAD(0, 0);
    H_LOAD(1, 64);

    for (int i = 0; i < NC; i++) {
        if (i + 2 < NC)      { H_LOAD((i + 2) & 3, (long)(i + 2) * 64); CP_WAIT(2); }
        else if (i + 1 < NC) { CP_WAIT(1); }
        else                 { CP_WAIT(0); }
        __syncthreads();   // single barrier per chunk: protects both stage-ready and stage-reuse
        const uint32_t As = sb + (uint32_t)(i & 3) * STAGE_H;
        const uint32_t Bs = As + 16384;

#pragma unroll
        for (int ks = 0; ks < 4; ks++) {
            uint32_t a[2][4], b[4][2];
#pragma unroll
            for (int mf = 0; mf < 2; mf++) {
                int row = arow_b + mf * 16;
                int ch = ks * 2 + ch_hi;
                ldsm_x4(a[mf], As + row * 128 + ((ch ^ (row & 7)) << 4));
            }
#pragma unroll
            for (int np = 0; np < 2; np++) {
                int row = brow_b + np * 16;
                int ch = ks * 2 + ch_hi;
                uint32_t q[4];
                ldsm_x4(q, Bs + row * 128 + ((ch ^ (row & 7)) << 4));
                b[np * 2][0]     = q[0]; b[np * 2][1]     = q[2];
                b[np * 2 + 1][0] = q[1]; b[np * 2 + 1][1] = q[3];
            }
#pragma unroll
            for (int mf = 0; mf < 2; mf++)
#pragma unroll
                for (int nf = 0; nf < 4; nf++)
                    mma16816h(acc[mf][nf], a[mf], b[nf]);
        }
    }

#pragma unroll
    for (int mf = 0; mf < 2; mf++)
#pragma unroll
        for (int nf = 0; nf < 4; nf++) {
            long row = row0 + wm * 32 + mf * 16 + (lane >> 2);
            long col = col0 + wn * 32 + nf * 8 + (lane & 3) * 2;
            if (OUT16) {
                *(uint32_t*)(C16 + row * ldC + col)       = pack_h2(acc[mf][nf][0], acc[mf][nf][1]);
                *(uint32_t*)(C16 + (row + 8) * ldC + col) = pack_h2(acc[mf][nf][2], acc[mf][nf][3]);
            } else {
                *(float2*)(Cf + row * ldC + col)       = make_float2(acc[mf][nf][0], acc[mf][nf][1]);
                *(float2*)(Cf + (row + 8) * ldC + col) = make_float2(acc[mf][nf][2], acc[mf][nf][3]);
            }
        }
#undef H_LOAD
}

// ======================= NN GEMM (fp16, 4-stage, 1 sync/chunk): C = A[M,K] @ B[K,N] ==============
#define STAGE_NN 32768u
#define GSMEM_NN (4 * STAGE_NN)
__global__ __launch_bounds__(512, 1)
void gemm_nn_f16(const __half* __restrict__ A, const __half* __restrict__ B,
                 float* __restrict__ Cf, int Kdim, long ldA, long ldB, long ldC)
{
    extern __shared__ char sm[];
    const uint32_t sb = smem_u32(sm);
    const int tid = threadIdx.x, wid = tid >> 5, lane = tid & 31;
    const int wm = wid >> 2, wn = wid & 3;
    const long row0 = (long)blockIdx.y * 128, col0 = (long)blockIdx.x * 128;
    const int NC = Kdim / 64;

    uint32_t soffA[2], soffB[2]; long aoff[2], boff[2];
#pragma unroll
    for (int j = 0; j < 2; j++) {
        int slot = tid + j * 512;
        int ra = slot >> 3, ca = slot & 7;
        soffA[j] = (uint32_t)(ra * 128 + ((ca ^ (ra & 7)) << 4));
        aoff[j]  = (row0 + ra) * ldA + ca * 8;
        int rb = slot >> 4, cb = slot & 15;
        soffB[j] = (uint32_t)(rb * 256 + ((cb ^ (rb & 7)) << 4));
        boff[j]  = (long)rb * ldB + col0 + cb * 8;
    }

    const int g = lane >> 3, lr = lane & 7;
    const int arow_b = wm * 32 + (g & 1) * 8 + lr;
    const int krow_b = (g & 1) * 8 + lr;
    const int bch_b  = wn * 4 + (g >> 1);

    float acc[2][4][4];
#pragma unroll
    for (int i = 0; i < 2; i++)
#pragma unroll
        for (int j = 0; j < 4; j++)
#pragma unroll
            for (int q = 0; q < 4; q++) acc[i][j][q] = 0.0f;

#define NN_LOAD(buf, kb) do {                                                  \
    uint32_t s_ = sb + (uint32_t)(buf) * STAGE_NN;                             \
    long kb_ = (kb);                                                           \
    _Pragma("unroll")                                                          \
    for (int j = 0; j < 2; j++) {                                              \
        CP16(s_ +         soffA[j], A + aoff[j] + kb_);                        \
        CP16(s_ + 16384 + soffB[j], B + boff[j] + kb_ * ldB);                  \
    }                                                                          \
    CP_COMMIT();                                                               \
} while (0)

    NN_LOAD(0, 0);
    NN_LOAD(1, 64);

    for (int i = 0; i < NC; i++) {
        if (i + 2 < NC)      { NN_LOAD((i + 2) & 3, (long)(i + 2) * 64); CP_WAIT(2); }
        else if (i + 1 < NC) { CP_WAIT(1); }
        else                 { CP_WAIT(0); }
        __syncthreads();
        const uint32_t As = sb + (uint32_t)(i & 3) * STAGE_NN;
        const uint32_t Bs = As + 16384;

#pragma unroll
        for (int ks = 0; ks < 4; ks++) {
            uint32_t a[2][4], b[4][2];
#pragma unroll
            for (int mf = 0; mf < 2; mf++) {
                int row = arow_b + mf * 16;
                int ch = ks * 2 + (g >> 1);
                ldsm_x4(a[mf], As + row * 128 + ((ch ^ (row & 7)) << 4));
            }
#pragma unroll
            for (int np = 0; np < 2; np++) {
                int krow = krow_b + ks * 16;
                int ch = bch_b + np * 2;
                uint32_t q[4];
                ldsm_x4_t(q, Bs + krow * 256 + ((ch ^ (krow & 7)) << 4));
                b[np * 2][0]     = q[0]; b[np * 2][1]     = q[1];
                b[np * 2 + 1][0] = q[2]; b[np * 2 + 1][1] = q[3];
            }
#pragma unroll
            for (int mf = 0; mf < 2; mf++)
#pragma unroll
                for (int nf = 0; nf < 4; nf++)
                    mma16816h(acc[mf][nf], a[mf], b[nf]);
        }
    }

#pragma unroll
    for (int mf = 0; mf < 2; mf++)
#pragma unroll
        for (int nf = 0; nf < 4; nf++) {
            long row = row0 + wm * 32 + mf * 16 + (lane >> 2);
            long col = col0 + wn * 32 + nf * 8 + (lane & 3) * 2;
            *(float2*)(Cf + row * ldC + col)       = make_float2(acc[mf][nf][0], acc[mf][nf][1]);
            *(float2*)(Cf + (row + 8) * ldC + col) = make_float2(acc[mf][nf][2], acc[mf][nf][3]);
        }
#undef NN_LOAD
}

// ======================= fp32 -> fp16 conversion =======================
__global__ __launch_bounds__(256)
void cvt_h1(const float* __restrict__ s, __half* __restrict__ d, long n4)
{
    for (long i = blockIdx.x * 256 + threadIdx.x; i < n4; i += (long)gridDim.x * 256) {
        float4 v = ((const float4*)s)[i];
        ((uint2*)d)[i] = make_uint2(pack_h2(v.x, v.y), pack_h2(v.z, v.w));
    }
}

// ======================= row softmax S -> P (fp16) =======================
__global__ __launch_bounds__(256)
void softmax_f16(const float* __restrict__ S, __half* __restrict__ P)
{
    const long row = blockIdx.x;
    const float4* rp = (const float4*)(S + row * (long)SEQ);
    const int tid = threadIdx.x;
    const float scale = 0.02209708691207961f;  // 1/sqrt(2048)

    float4 v[8];
    float mx = -INFINITY;
#pragma unroll
    for (int i = 0; i < 8; i++) {
        v[i] = rp[tid + i * 256];
        mx = fmaxf(mx, fmaxf(fmaxf(v[i].x, v[i].y), fmaxf(v[i].z, v[i].w)));
    }

    __shared__ float red[256];
    red[tid] = mx;
    __syncthreads();
    for (int s = 128; s > 0; s >>= 1) {
        if (tid < s) red[tid] = fmaxf(red[tid], red[tid + s]);
        __syncthreads();
    }
    mx = red[0];
    __syncthreads();

    float sum = 0.0f;
#pragma unroll
    for (int i = 0; i < 8; i++) {
        v[i].x = __expf((v[i].x - mx) * scale);
        v[i].y = __expf((v[i].y - mx) * scale);
        v[i].z = __expf((v[i].z - mx) * scale);
        v[i].w = __expf((v[i].w - mx) * scale);
        sum += (v[i].x + v[i].y) + (v[i].z + v[i].w);
    }
    red[tid] = sum;
    __syncthreads();
    for (int s = 128; s > 0; s >>= 1) {
        if (tid < s) red[tid] += red[tid + s];
        __syncthreads();
    }
    const float inv = 1.0f / red[0];

#pragma unroll
    for (int i = 0; i < 8; i++) {
        long idx = row * (long)SEQ + (long)(tid + i * 256) * 4;
        ((uint2*)(P + idx))[0] = make_uint2(pack_h2(v[i].x * inv, v[i].y * inv),
                                            pack_h2(v[i].z * inv, v[i].w * inv));
    }
}

// ======================= launch =======================
extern "C" void kernel_launch(void* const* d_in, const int* in_sizes, int n_in,
                              void* d_out, int out_size)
{
    (void)in_sizes; (void)n_in; (void)out_size;
    const float* X  = (const float*)d_in[0];
    const float* Wq = (const float*)d_in[1];
    const float* Wk = (const float*)d_in[2];
    const float* Wv = (const float*)d_in[3];
    float* O = (float*)d_out;

    __half *X16, *Wq16, *Wk16, *Wv16, *Q16, *K16, *V16, *P16;
    float* Smat;
    cudaGetSymbolAddress((void**)&X16, g_X16);
    cudaGetSymbolAddress((void**)&Wq16, g_Wq16);
    cudaGetSymbolAddress((void**)&Wk16, g_Wk16);
    cudaGetSymbolAddress((void**)&Wv16, g_Wv16);
    cudaGetSymbolAddress((void**)&Q16, g_Q16);
    cudaGetSymbolAddress((void**)&K16, g_K16);
    cudaGetSymbolAddress((void**)&V16, g_V16);
    cudaGetSymbolAddress((void**)&P16, g_P16);
    cudaGetSymbolAddress((void**)&Smat, g_S);

    cudaFuncSetAttribute(gemm_nt_h<1>, cudaFuncAttributeMaxDynamicSharedMemorySize, GSMEM_H);
    cudaFuncSetAttribute(gemm_nt_h<0>, cudaFuncAttributeMaxDynamicSharedMemorySize, GSMEM_H);
    cudaFuncSetAttribute(gemm_nn_f16,  cudaFuncAttributeMaxDynamicSharedMemorySize, GSMEM_NN);

    // 1) conversions: everything -> single fp16
    cvt_h1<<<2048, 256>>>(X,  X16,  (long)SEQ * DM / 4);
    cvt_h1<<<1024, 256>>>(Wq, Wq16, (long)DM * DM / 4);
    cvt_h1<<<1024, 256>>>(Wk, Wk16, (long)DM * DM / 4);
    cvt_h1<<<1024, 256>>>(Wv, Wv16, (long)DM * DM / 4);

    dim3 blk(512);
    // 2) projections (fp16 1-term): Q/K/V = X16 @ W16^T -> fp16
    dim3 gp(DM / 128, SEQ / 128);
    gemm_nt_h<1><<<gp, blk, GSMEM_H>>>(X16, Wq16, nullptr, Q16, DM, DM, DM, DM);
    gemm_nt_h<1><<<gp, blk, GSMEM_H>>>(X16, Wk16, nullptr, K16, DM, DM, DM, DM);
    gemm_nt_h<1><<<gp, blk, GSMEM_H>>>(X16, Wv16, nullptr, V16, DM, DM, DM, DM);

    // 3) S = Q16 @ K16^T (fp16 1-term) -> fp32
    dim3 gs(SEQ / 128, SEQ / 128);
    gemm_nt_h<0><<<gs, blk, GSMEM_H>>>(Q16, K16, Smat, nullptr, DM, DM, DM, SEQ);

    // 4) P = softmax(S / sqrt(DM)) -> fp16
    softmax_f16<<<SEQ, 256>>>(Smat, P16);

    // 5) O = P @ V (fp16 NN) -> fp32
    dim3 go(DM / 128, SEQ / 128);
    gemm_nn_f16<<<go, blk, GSMEM_NN>>>(P16, V16, O, SEQ, SEQ, DM, DM);
}

// round 12
// speedup vs baseline: 1.8968x; 1.0216x over previous
#include <cuda_runtime.h>
#include <cuda_fp16.h>
#include <cstdint>
#include <math.h>

#define SEQ 8192
#define DM  2048

// ======================= scratch (device globals) =======================
__device__ __half g_X16[(size_t)SEQ * DM];
__device__ __half g_Wq16[(size_t)DM * DM], g_Wk16[(size_t)DM * DM], g_Wv16[(size_t)DM * DM];
__device__ __half g_Q16[(size_t)SEQ * DM], g_K16[(size_t)SEQ * DM], g_V16[(size_t)SEQ * DM];
__device__ float  g_S[(size_t)SEQ * SEQ];
__device__ __half g_P16[(size_t)SEQ * SEQ];

// ======================= helpers =======================
__device__ __forceinline__ uint32_t smem_u32(const void* p) {
    uint32_t a;
    asm("{ .reg .u64 t; cvta.to.shared.u64 t, %1; cvt.u32.u64 %0, t; }" : "=r"(a) : "l"(p));
    return a;
}
#define CP16(sm, gp) \
    asm volatile("cp.async.cg.shared.global [%0], [%1], 16;" :: "r"(sm), "l"(gp))
#define CP_COMMIT() asm volatile("cp.async.commit_group;")
#define CP_WAIT(n)  asm volatile("cp.async.wait_group %0;" :: "n"(n) : "memory")

__device__ __forceinline__ void ldsm_x4(uint32_t* r, uint32_t a) {
    asm volatile("ldmatrix.sync.aligned.m8n8.x4.shared.b16 {%0,%1,%2,%3}, [%4];"
        : "=r"(r[0]), "=r"(r[1]), "=r"(r[2]), "=r"(r[3]) : "r"(a));
}
__device__ __forceinline__ void ldsm_x4_t(uint32_t* r, uint32_t a) {
    asm volatile("ldmatrix.sync.aligned.m8n8.x4.trans.shared.b16 {%0,%1,%2,%3}, [%4];"
        : "=r"(r[0]), "=r"(r[1]), "=r"(r[2]), "=r"(r[3]) : "r"(a));
}
__device__ __forceinline__ void mma16816h(float* c, const uint32_t* a, const uint32_t* b) {
    asm volatile("mma.sync.aligned.m16n8k16.row.col.f32.f16.f16.f32 "
        "{%0,%1,%2,%3}, {%4,%5,%6,%7}, {%8,%9}, {%0,%1,%2,%3};"
        : "+f"(c[0]), "+f"(c[1]), "+f"(c[2]), "+f"(c[3])
        : "r"(a[0]), "r"(a[1]), "r"(a[2]), "r"(a[3]), "r"(b[0]), "r"(b[1]));
}
__device__ __forceinline__ uint32_t pack_h2(float a, float b) {
    __half2 h = __floats2half2_rn(a, b);
    return *(uint32_t*)&h;
}

// ======================= NT GEMM 128x256: C[M,N] = A16[M,K] @ B16[N,K]^T =======================
// 16 warps, warp tile 32x64. 4-stage, 2-ahead prefetch, 1 sync/chunk. OUT16: fp16 out (else fp32).
#define STAGE_H (48u * 1024u)
#define GSMEM_H (4 * STAGE_H)
template <int OUT16>
__global__ __launch_bounds__(512, 1)
void gemm_nt_h(const __half* __restrict__ A, const __half* __restrict__ B,
               float* __restrict__ Cf, __half* __restrict__ C16,
               int Kdim, long ldA, long ldB, long ldC)
{
    extern __shared__ char sm[];
    const uint32_t sb = smem_u32(sm);
    const int tid = threadIdx.x, wid = tid >> 5, lane = tid & 31;
    const int wm = wid >> 2, wn = wid & 3;           // 4x4 warps; warp tile 32m x 64n
    const long row0 = (long)blockIdx.y * 128, col0 = (long)blockIdx.x * 256;
    const int NC = Kdim / 64;

    // A loader: 1024 slots (128 rows x 8 chunks), 2/thread. B loader: 2048 slots (256 rows), 4/thread.
    uint32_t soffA[2]; long aoff[2];
#pragma unroll
    for (int j = 0; j < 2; j++) {
        int slot = tid + j * 512;
        int r = slot >> 3, c = slot & 7;
        soffA[j] = (uint32_t)(r * 128 + ((c ^ (r & 7)) << 4));
        aoff[j]  = (row0 + r) * ldA + c * 8;
    }
    uint32_t soffB[4]; long boff[4];
#pragma unroll
    for (int j = 0; j < 4; j++) {
        int slot = tid + j * 512;
        int r = slot >> 3, c = slot & 7;
        soffB[j] = (uint32_t)(16384 + r * 128 + ((c ^ (r & 7)) << 4));
        boff[j]  = (col0 + r) * ldB + c * 8;
    }

    const int g = lane >> 3, lr = lane & 7;
    const int arow_b = wm * 32 + (g & 1) * 8 + lr;   // + mf*16
    const int brow_b = wn * 64 + (g & 1) * 8 + lr;   // + np*16
    const int ch_hi = g >> 1;

    float acc[2][8][4];
#pragma unroll
    for (int i = 0; i < 2; i++)
#pragma unroll
        for (int j = 0; j < 8; j++)
#pragma unroll
            for (int q = 0; q < 4; q++) acc[i][j][q] = 0.0f;

#define H_LOAD(buf, kb) do {                                                   \
    uint32_t s_ = sb + (uint32_t)(buf) * STAGE_H;                              \
    _Pragma("unroll")                                                          \
    for (int j = 0; j < 2; j++) CP16(s_ + soffA[j], A + aoff[j] + (kb));       \
    _Pragma("unroll")                                                          \
    for (int j = 0; j < 4; j++) CP16(s_ + soffB[j], B + boff[j] + (kb));       \
    CP_COMMIT();                                                               \
} while (0)

    H_LOAD(0, 0);
    H_LOAD(1, 64);

    for (int i = 0; i < NC; i++) {
        if (i + 2 < NC)      { H_LOAD((i + 2) & 3, (long)(i + 2) * 64); CP_WAIT(2); }
        else if (i + 1 < NC) { CP_WAIT(1); }
        else                 { CP_WAIT(0); }
        __syncthreads();   // single barrier per chunk
        const uint32_t As = sb + (uint32_t)(i & 3) * STAGE_H;
        const uint32_t Bs = As + 16384;

#pragma unroll
        for (int ks = 0; ks < 4; ks++) {
            uint32_t a[2][4], b[8][2];
#pragma unroll
            for (int mf = 0; mf < 2; mf++) {
                int row = arow_b + mf * 16;
                int ch = ks * 2 + ch_hi;
                ldsm_x4(a[mf], As + row * 128 + ((ch ^ (row & 7)) << 4));
            }
#pragma unroll
            for (int np = 0; np < 4; np++) {
                int row = brow_b + np * 16;
                int ch = ks * 2 + ch_hi;
                uint32_t q[4];
                ldsm_x4(q, Bs + row * 128 + ((ch ^ (row & 7)) << 4));
                b[np * 2][0]     = q[0]; b[np * 2][1]     = q[2];
                b[np * 2 + 1][0] = q[1]; b[np * 2 + 1][1] = q[3];
            }
#pragma unroll
            for (int mf = 0; mf < 2; mf++)
#pragma unroll
                for (int nf = 0; nf < 8; nf++)
                    mma16816h(acc[mf][nf], a[mf], b[nf]);
        }
    }

#pragma unroll
    for (int mf = 0; mf < 2; mf++)
#pragma unroll
        for (int nf = 0; nf < 8; nf++) {
            long row = row0 + wm * 32 + mf * 16 + (lane >> 2);
            long col = col0 + wn * 64 + nf * 8 + (lane & 3) * 2;
            if (OUT16) {
                *(uint32_t*)(C16 + row * ldC + col)       = pack_h2(acc[mf][nf][0], acc[mf][nf][1]);
                *(uint32_t*)(C16 + (row + 8) * ldC + col) = pack_h2(acc[mf][nf][2], acc[mf][nf][3]);
            } else {
                *(float2*)(Cf + row * ldC + col)       = make_float2(acc[mf][nf][0], acc[mf][nf][1]);
                *(float2*)(Cf + (row + 8) * ldC + col) = make_float2(acc[mf][nf][2], acc[mf][nf][3]);
            }
        }
#undef H_LOAD
}

// ======================= NN GEMM (fp16, 4-stage, 1 sync/chunk): C = A[M,K] @ B[K,N] ==============
#define STAGE_NN 32768u
#define GSMEM_NN (4 * STAGE_NN)
__global__ __launch_bounds__(512, 1)
void gemm_nn_f16(const __half* __restrict__ A, const __half* __restrict__ B,
                 float* __restrict__ Cf, int Kdim, long ldA, long ldB, long ldC)
{
    extern __shared__ char sm[];
    const uint32_t sb = smem_u32(sm);
    const int tid = threadIdx.x, wid = tid >> 5, lane = tid & 31;
    const int wm = wid >> 2, wn = wid & 3;
    const long row0 = (long)blockIdx.y * 128, col0 = (long)blockIdx.x * 128;
    const int NC = Kdim / 64;

    uint32_t soffA[2], soffB[2]; long aoff[2], boff[2];
#pragma unroll
    for (int j = 0; j < 2; j++) {
        int slot = tid + j * 512;
        int ra = slot >> 3, ca = slot & 7;
        soffA[j] = (uint32_t)(ra * 128 + ((ca ^ (ra & 7)) << 4));
        aoff[j]  = (row0 + ra) * ldA + ca * 8;
        int rb = slot >> 4, cb = slot & 15;
        soffB[j] = (uint32_t)(rb * 256 + ((cb ^ (rb & 7)) << 4));
        boff[j]  = (long)rb * ldB + col0 + cb * 8;
    }

    const int g = lane >> 3, lr = lane & 7;
    const int arow_b = wm * 32 + (g & 1) * 8 + lr;
    const int krow_b = (g & 1) * 8 + lr;
    const int bch_b  = wn * 4 + (g >> 1);

    float acc[2][4][4];
#pragma unroll
    for (int i = 0; i < 2; i++)
#pragma unroll
        for (int j = 0; j < 4; j++)
#pragma unroll
            for (int q = 0; q < 4; q++) acc[i][j][q] = 0.0f;

#define NN_LOAD(buf, kb) do {                                                  \
    uint32_t s_ = sb + (uint32_t)(buf) * STAGE_NN;                             \
    long kb_ = (kb);                                                           \
    _Pragma("unroll")                                                          \
    for (int j = 0; j < 2; j++) {                                              \
        CP16(s_ +         soffA[j], A + aoff[j] + kb_);                        \
        CP16(s_ + 16384 + soffB[j], B + boff[j] + kb_ * ldB);                  \
    }                                                                          \
    CP_COMMIT();                                                               \
} while (0)

    NN_LOAD(0, 0);
    NN_LOAD(1, 64);

    for (int i = 0; i < NC; i++) {
        if (i + 2 < NC)      { NN_LOAD((i + 2) & 3, (long)(i + 2) * 64); CP_WAIT(2); }
        else if (i + 1 < NC) { CP_WAIT(1); }
        else                 { CP_WAIT(0); }
        __syncthreads();
        const uint32_t As = sb + (uint32_t)(i & 3) * STAGE_NN;
        const uint32_t Bs = As + 16384;

#pragma unroll
        for (int ks = 0; ks < 4; ks++) {
            uint32_t a[2][4], b[4][2];
#pragma unroll
            for (int mf = 0; mf < 2; mf++) {
                int row = arow_b + mf * 16;
                int ch = ks * 2 + (g >> 1);
                ldsm_x4(a[mf], As + row * 128 + ((ch ^ (row & 7)) << 4));
            }
#pragma unroll
            for (int np = 0; np < 2; np++) {
                int krow = krow_b + ks * 16;
                int ch = bch_b + np * 2;
                uint32_t q[4];
                ldsm_x4_t(q, Bs + krow * 256 + ((ch ^ (krow & 7)) << 4));
                b[np * 2][0]     = q[0]; b[np * 2][1]     = q[1];
                b[np * 2 + 1][0] = q[2]; b[np * 2 + 1][1] = q[3];
            }
#pragma unroll
            for (int mf = 0; mf < 2; mf++)
#pragma unroll
                for (int nf = 0; nf < 4; nf++)
                    mma16816h(acc[mf][nf], a[mf], b[nf]);
        }
    }

#pragma unroll
    for (int mf = 0; mf < 2; mf++)
#pragma unroll
        for (int nf = 0; nf < 4; nf++) {
            long row = row0 + wm * 32 + mf * 16 + (lane >> 2);
            long col = col0 + wn * 32 + nf * 8 + (lane & 3) * 2;
            *(float2*)(Cf + row * ldC + col)       = make_float2(acc[mf][nf][0], acc[mf][nf][1]);
            *(float2*)(Cf + (row + 8) * ldC + col) = make_float2(acc[mf][nf][2], acc[mf][nf][3]);
        }
#undef NN_LOAD
}

// ======================= fp32 -> fp16 conversion =======================
__global__ __launch_bounds__(256)
void cvt_h1(const float* __restrict__ s, __half* __restrict__ d, long n4)
{
    for (long i = blockIdx.x * 256 + threadIdx.x; i < n4; i += (long)gridDim.x * 256) {
        float4 v = ((const float4*)s)[i];
        ((uint2*)d)[i] = make_uint2(pack_h2(v.x, v.y), pack_h2(v.z, v.w));
    }
}

// ======================= row softmax S -> P (fp16) =======================
__global__ __launch_bounds__(256)
void softmax_f16(const float* __restrict__ S, __half* __restrict__ P)
{
    const long row = blockIdx.x;
    const float4* rp = (const float4*)(S + row * (long)SEQ);
    const int tid = threadIdx.x;
    const float scale = 0.02209708691207961f;  // 1/sqrt(2048)

    float4 v[8];
    float mx = -INFINITY;
#pragma unroll
    for (int i = 0; i < 8; i++) {
        v[i] = rp[tid + i * 256];
        mx = fmaxf(mx, fmaxf(fmaxf(v[i].x, v[i].y), fmaxf(v[i].z, v[i].w)));
    }

    __shared__ float red[256];
    red[tid] = mx;
    __syncthreads();
    for (int s = 128; s > 0; s >>= 1) {
        if (tid < s) red[tid] = fmaxf(red[tid], red[tid + s]);
        __syncthreads();
    }
    mx = red[0];
    __syncthreads();

    float sum = 0.0f;
#pragma unroll
    for (int i = 0; i < 8; i++) {
        v[i].x = __expf((v[i].x - mx) * scale);
        v[i].y = __expf((v[i].y - mx) * scale);
        v[i].z = __expf((v[i].z - mx) * scale);
        v[i].w = __expf((v[i].w - mx) * scale);
        sum += (v[i].x + v[i].y) + (v[i].z + v[i].w);
    }
    red[tid] = sum;
    __syncthreads();
    for (int s = 128; s > 0; s >>= 1) {
        if (tid < s) red[tid] += red[tid + s];
        __syncthreads();
    }
    const float inv = 1.0f / red[0];

#pragma unroll
    for (int i = 0; i < 8; i++) {
        long idx = row * (long)SEQ + (long)(tid + i * 256) * 4;
        ((uint2*)(P + idx))[0] = make_uint2(pack_h2(v[i].x * inv, v[i].y * inv),
                                            pack_h2(v[i].z * inv, v[i].w * inv));
    }
}

// ======================= launch =======================
extern "C" void kernel_launch(void* const* d_in, const int* in_sizes, int n_in,
                              void* d_out, int out_size)
{
    (void)in_sizes; (void)n_in; (void)out_size;
    const float* X  = (const float*)d_in[0];
    const float* Wq = (const float*)d_in[1];
    const float* Wk = (const float*)d_in[2];
    const float* Wv = (const float*)d_in[3];
    float* O = (float*)d_out;

    __half *X16, *Wq16, *Wk16, *Wv16, *Q16, *K16, *V16, *P16;
    float* Smat;
    cudaGetSymbolAddress((void**)&X16, g_X16);
    cudaGetSymbolAddress((void**)&Wq16, g_Wq16);
    cudaGetSymbolAddress((void**)&Wk16, g_Wk16);
    cudaGetSymbolAddress((void**)&Wv16, g_Wv16);
    cudaGetSymbolAddress((void**)&Q16, g_Q16);
    cudaGetSymbolAddress((void**)&K16, g_K16);
    cudaGetSymbolAddress((void**)&V16, g_V16);
    cudaGetSymbolAddress((void**)&P16, g_P16);
    cudaGetSymbolAddress((void**)&Smat, g_S);

    cudaFuncSetAttribute(gemm_nt_h<1>, cudaFuncAttributeMaxDynamicSharedMemorySize, GSMEM_H);
    cudaFuncSetAttribute(gemm_nt_h<0>, cudaFuncAttributeMaxDynamicSharedMemorySize, GSMEM_H);
    cudaFuncSetAttribute(gemm_nn_f16,  cudaFuncAttributeMaxDynamicSharedMemorySize, GSMEM_NN);

    // 1) conversions: everything -> single fp16
    cvt_h1<<<2048, 256>>>(X,  X16,  (long)SEQ * DM / 4);
    cvt_h1<<<1024, 256>>>(Wq, Wq16, (long)DM * DM / 4);
    cvt_h1<<<1024, 256>>>(Wk, Wk16, (long)DM * DM / 4);
    cvt_h1<<<1024, 256>>>(Wv, Wv16, (long)DM * DM / 4);

    dim3 blk(512);
    // 2) projections (fp16 1-term): Q/K/V = X16 @ W16^T -> fp16  (CTA tile 128x256)
    dim3 gp(DM / 256, SEQ / 128);
    gemm_nt_h<1><<<gp, blk, GSMEM_H>>>(X16, Wq16, nullptr, Q16, DM, DM, DM, DM);
    gemm_nt_h<1><<<gp, blk, GSMEM_H>>>(X16, Wk16, nullptr, K16, DM, DM, DM, DM);
    gemm_nt_h<1><<<gp, blk, GSMEM_H>>>(X16, Wv16, nullptr, V16, DM, DM, DM, DM);

    // 3) S = Q16 @ K16^T (fp16 1-term) -> fp32  (CTA tile 128x256)
    dim3 gs(SEQ / 256, SEQ / 128);
    gemm_nt_h<0><<<gs, blk, GSMEM_H>>>(Q16, K16, Smat, nullptr, DM, DM, DM, SEQ);

    // 4) P = softmax(S / sqrt(DM)) -> fp16
    softmax_f16<<<SEQ, 256>>>(Smat, P16);

    // 5) O = P @ V (fp16 NN) -> fp32
    dim3 go(DM / 128, SEQ / 128);
    gemm_nn_f16<<<go, blk, GSMEM_NN>>>(P16, V16, O, SEQ, SEQ, DM, DM);
}

// round 15
// speedup vs baseline: 1.9138x; 1.0090x over previous
#include <cuda_runtime.h>
#include <cuda_fp16.h>
#include <cstdint>
#include <math.h>

#define SEQ 8192
#define DM  2048

// ======================= scratch (device globals) =======================
__device__ __half g_X16[(size_t)SEQ * DM];
__device__ __half g_Wq16[(size_t)DM * DM], g_Wk16[(size_t)DM * DM], g_Wv16[(size_t)DM * DM];
__device__ __half g_Q16[(size_t)SEQ * DM], g_K16[(size_t)SEQ * DM], g_V16[(size_t)SEQ * DM];
__device__ __half g_S16[(size_t)SEQ * SEQ];
__device__ __half g_P16[(size_t)SEQ * SEQ];

// ======================= helpers =======================
__device__ __forceinline__ uint32_t smem_u32(const void* p) {
    uint32_t a;
    asm("{ .reg .u64 t; cvta.to.shared.u64 t, %1; cvt.u32.u64 %0, t; }" : "=r"(a) : "l"(p));
    return a;
}
#define CP16(sm, gp) \
    asm volatile("cp.async.cg.shared.global [%0], [%1], 16;" :: "r"(sm), "l"(gp))
#define CP_COMMIT() asm volatile("cp.async.commit_group;")
#define CP_WAIT(n)  asm volatile("cp.async.wait_group %0;" :: "n"(n) : "memory")

__device__ __forceinline__ void ldsm_x4(uint32_t* r, uint32_t a) {
    asm volatile("ldmatrix.sync.aligned.m8n8.x4.shared.b16 {%0,%1,%2,%3}, [%4];"
        : "=r"(r[0]), "=r"(r[1]), "=r"(r[2]), "=r"(r[3]) : "r"(a));
}
__device__ __forceinline__ void ldsm_x4_t(uint32_t* r, uint32_t a) {
    asm volatile("ldmatrix.sync.aligned.m8n8.x4.trans.shared.b16 {%0,%1,%2,%3}, [%4];"
        : "=r"(r[0]), "=r"(r[1]), "=r"(r[2]), "=r"(r[3]) : "r"(a));
}
__device__ __forceinline__ void mma16816h(float* c, const uint32_t* a, const uint32_t* b) {
    asm volatile("mma.sync.aligned.m16n8k16.row.col.f32.f16.f16.f32 "
        "{%0,%1,%2,%3}, {%4,%5,%6,%7}, {%8,%9}, {%0,%1,%2,%3};"
        : "+f"(c[0]), "+f"(c[1]), "+f"(c[2]), "+f"(c[3])
        : "r"(a[0]), "r"(a[1]), "r"(a[2]), "r"(a[3]), "r"(b[0]), "r"(b[1]));
}
__device__ __forceinline__ uint32_t pack_h2(float a, float b) {
    __half2 h = __floats2half2_rn(a, b);
    return *(uint32_t*)&h;
}

// ======================= NT GEMM 128x256: C[M,N] = A16[M,K] @ B16[N,K]^T =======================
// 16 warps, warp tile 32x64. 4-stage, 2-ahead prefetch, 1 sync/chunk. OUT16: fp16 out (else fp32).
#define STAGE_H (48u * 1024u)
#define GSMEM_H (4 * STAGE_H)
template <int OUT16>
__global__ __launch_bounds__(512, 1)
void gemm_nt_h(const __half* __restrict__ A, const __half* __restrict__ B,
               float* __restrict__ Cf, __half* __restrict__ C16,
               int Kdim, long ldA, long ldB, long ldC)
{
    extern __shared__ char sm[];
    const uint32_t sb = smem_u32(sm);
    const int tid = threadIdx.x, wid = tid >> 5, lane = tid & 31;
    const int wm = wid >> 2, wn = wid & 3;
    const long row0 = (long)blockIdx.y * 128, col0 = (long)blockIdx.x * 256;
    const int NC = Kdim / 64;

    uint32_t soffA[2]; long aoff[2];
#pragma unroll
    for (int j = 0; j < 2; j++) {
        int slot = tid + j * 512;
        int r = slot >> 3, c = slot & 7;
        soffA[j] = (uint32_t)(r * 128 + ((c ^ (r & 7)) << 4));
        aoff[j]  = (row0 + r) * ldA + c * 8;
    }
    uint32_t soffB[4]; long boff[4];
#pragma unroll
    for (int j = 0; j < 4; j++) {
        int slot = tid + j * 512;
        int r = slot >> 3, c = slot & 7;
        soffB[j] = (uint32_t)(16384 + r * 128 + ((c ^ (r & 7)) << 4));
        boff[j]  = (col0 + r) * ldB + c * 8;
    }

    const int g = lane >> 3, lr = lane & 7;
    const int arow_b = wm * 32 + (g & 1) * 8 + lr;
    const int brow_b = wn * 64 + (g & 1) * 8 + lr;
    const int ch_hi = g >> 1;

    float acc[2][8][4];
#pragma unroll
    for (int i = 0; i < 2; i++)
#pragma unroll
        for (int j = 0; j < 8; j++)
#pragma unroll
            for (int q = 0; q < 4; q++) acc[i][j][q] = 0.0f;

#define H_LOAD(buf, kb) do {                                                   \
    uint32_t s_ = sb + (uint32_t)(buf) * STAGE_H;                              \
    _Pragma("unroll")                                                          \
    for (int j = 0; j < 2; j++) CP16(s_ + soffA[j], A + aoff[j] + (kb));       \
    _Pragma("unroll")                                                          \
    for (int j = 0; j < 4; j++) CP16(s_ + soffB[j], B + boff[j] + (kb));       \
    CP_COMMIT();                                                               \
} while (0)

    H_LOAD(0, 0);
    H_LOAD(1, 64);

    for (int i = 0; i < NC; i++) {
        if (i + 2 < NC)      { H_LOAD((i + 2) & 3, (long)(i + 2) * 64); CP_WAIT(2); }
        else if (i + 1 < NC) { CP_WAIT(1); }
        else                 { CP_WAIT(0); }
        __syncthreads();   // single barrier per chunk
        const uint32_t As = sb + (uint32_t)(i & 3) * STAGE_H;
        const uint32_t Bs = As + 16384;

#pragma unroll
        for (int ks = 0; ks < 4; ks++) {
            uint32_t a[2][4], b[8][2];
#pragma unroll
            for (int mf = 0; mf < 2; mf++) {
                int row = arow_b + mf * 16;
                int ch = ks * 2 + ch_hi;
                ldsm_x4(a[mf], As + row * 128 + ((ch ^ (row & 7)) << 4));
            }
#pragma unroll
            for (int np = 0; np < 4; np++) {
                int row = brow_b + np * 16;
                int ch = ks * 2 + ch_hi;
                uint32_t q[4];
                ldsm_x4(q, Bs + row * 128 + ((ch ^ (row & 7)) << 4));
                b[np * 2][0]     = q[0]; b[np * 2][1]     = q[2];
                b[np * 2 + 1][0] = q[1]; b[np * 2 + 1][1] = q[3];
            }
#pragma unroll
            for (int mf = 0; mf < 2; mf++)
#pragma unroll
                for (int nf = 0; nf < 8; nf++)
                    mma16816h(acc[mf][nf], a[mf], b[nf]);
        }
    }

#pragma unroll
    for (int mf = 0; mf < 2; mf++)
#pragma unroll
        for (int nf = 0; nf < 8; nf++) {
            long row = row0 + wm * 32 + mf * 16 + (lane >> 2);
            long col = col0 + wn * 64 + nf * 8 + (lane & 3) * 2;
            if (OUT16) {
                *(uint32_t*)(C16 + row * ldC + col)       = pack_h2(acc[mf][nf][0], acc[mf][nf][1]);
                *(uint32_t*)(C16 + (row + 8) * ldC + col) = pack_h2(acc[mf][nf][2], acc[mf][nf][3]);
            } else {
                *(float2*)(Cf + row * ldC + col)       = make_float2(acc[mf][nf][0], acc[mf][nf][1]);
                *(float2*)(Cf + (row + 8) * ldC + col) = make_float2(acc[mf][nf][2], acc[mf][nf][3]);
            }
        }
#undef H_LOAD
}

// ======================= NN GEMM (fp16, 4-stage, 1 sync/chunk): C = A[M,K] @ B[K,N] ==============
// Exact R12 version (128x128 tile).
#define STAGE_NN 32768u
#define GSMEM_NN (4 * STAGE_NN)
__global__ __launch_bounds__(512, 1)
void gemm_nn_f16(const __half* __restrict__ A, const __half* __restrict__ B,
                 float* __restrict__ Cf, int Kdim, long ldA, long ldB, long ldC)
{
    extern __shared__ char sm[];
    const uint32_t sb = smem_u32(sm);
    const int tid = threadIdx.x, wid = tid >> 5, lane = tid & 31;
    const int wm = wid >> 2, wn = wid & 3;
    const long row0 = (long)blockIdx.y * 128, col0 = (long)blockIdx.x * 128;
    const int NC = Kdim / 64;

    uint32_t soffA[2], soffB[2]; long aoff[2], boff[2];
#pragma unroll
    for (int j = 0; j < 2; j++) {
        int slot = tid + j * 512;
        int ra = slot >> 3, ca = slot & 7;
        soffA[j] = (uint32_t)(ra * 128 + ((ca ^ (ra & 7)) << 4));
        aoff[j]  = (row0 + ra) * ldA + ca * 8;
        int rb = slot >> 4, cb = slot & 15;
        soffB[j] = (uint32_t)(rb * 256 + ((cb ^ (rb & 7)) << 4));
        boff[j]  = (long)rb * ldB + col0 + cb * 8;
    }

    const int g = lane >> 3, lr = lane & 7;
    const int arow_b = wm * 32 + (g & 1) * 8 + lr;
    const int krow_b = (g & 1) * 8 + lr;
    const int bch_b  = wn * 4 + (g >> 1);

    float acc[2][4][4];
#pragma unroll
    for (int i = 0; i < 2; i++)
#pragma unroll
        for (int j = 0; j < 4; j++)
#pragma unroll
            for (int q = 0; q < 4; q++) acc[i][j][q] = 0.0f;

#define NN_LOAD(buf, kb) do {                                                  \
    uint32_t s_ = sb + (uint32_t)(buf) * STAGE_NN;                             \
    long kb_ = (kb);                                                           \
    _Pragma("unroll")                                                          \
    for (int j = 0; j < 2; j++) {                                              \
        CP16(s_ +         soffA[j], A + aoff[j] + kb_);                        \
        CP16(s_ + 16384 + soffB[j], B + boff[j] + kb_ * ldB);                  \
    }                                                                          \
    CP_COMMIT();                                                               \
} while (0)

    NN_LOAD(0, 0);
    NN_LOAD(1, 64);

    for (int i = 0; i < NC; i++) {
        if (i + 2 < NC)      { NN_LOAD((i + 2) & 3, (long)(i + 2) * 64); CP_WAIT(2); }
        else if (i + 1 < NC) { CP_WAIT(1); }
        else                 { CP_WAIT(0); }
        __syncthreads();
        const uint32_t As = sb + (uint32_t)(i & 3) * STAGE_NN;
        const uint32_t Bs = As + 16384;

#pragma unroll
        for (int ks = 0; ks < 4; ks++) {
            uint32_t a[2][4], b[4][2];
#pragma unroll
            for (int mf = 0; mf < 2; mf++) {
                int row = arow_b + mf * 16;
                int ch = ks * 2 + (g >> 1);
                ldsm_x4(a[mf], As + row * 128 + ((ch ^ (row & 7)) << 4));
            }
#pragma unroll
            for (int np = 0; np < 2; np++) {
                int krow = krow_b + ks * 16;
                int ch = bch_b + np * 2;
                uint32_t q[4];
                ldsm_x4_t(q, Bs + krow * 256 + ((ch ^ (krow & 7)) << 4));
                b[np * 2][0]     = q[0]; b[np * 2][1]     = q[1];
                b[np * 2 + 1][0] = q[2]; b[np * 2 + 1][1] = q[3];
            }
#pragma unroll
            for (int mf = 0; mf < 2; mf++)
#pragma unroll
                for (int nf = 0; nf < 4; nf++)
                    mma16816h(acc[mf][nf], a[mf], b[nf]);
        }
    }

#pragma unroll
    for (int mf = 0; mf < 2; mf++)
#pragma unroll
        for (int nf = 0; nf < 4; nf++) {
            long row = row0 + wm * 32 + mf * 16 + (lane >> 2);
            long col = col0 + wn * 32 + nf * 8 + (lane & 3) * 2;
            *(float2*)(Cf + row * ldC + col)       = make_float2(acc[mf][nf][0], acc[mf][nf][1]);
            *(float2*)(Cf + (row + 8) * ldC + col) = make_float2(acc[mf][nf][2], acc[mf][nf][3]);
        }
#undef NN_LOAD
}

// ======================= fp32 -> fp16 conversion =======================
__global__ __launch_bounds__(256)
void cvt_h1(const float* __restrict__ s, __half* __restrict__ d, long n4)
{
    for (long i = blockIdx.x * 256 + threadIdx.x; i < n4; i += (long)gridDim.x * 256) {
        float4 v = ((const float4*)s)[i];
        ((uint2*)d)[i] = make_uint2(pack_h2(v.x, v.y), pack_h2(v.z, v.w));
    }
}

// ======================= row softmax: S16 (fp16 logits, pre-scale) -> P16 =======================
__global__ __launch_bounds__(256)
void softmax_f16(const __half* __restrict__ S, __half* __restrict__ P)
{
    const long row = blockIdx.x;
    const uint4* rp = (const uint4*)(S + row * (long)SEQ);  // 8 halves per uint4
    const int tid = threadIdx.x;
    const float scale = 0.02209708691207961f;  // 1/sqrt(2048)

    float v[32];
    float mx = -INFINITY;
#pragma unroll
    for (int i = 0; i < 4; i++) {
        uint4 u = rp[tid + i * 256];
        const uint32_t w[4] = {u.x, u.y, u.z, u.w};
#pragma unroll
        for (int j = 0; j < 4; j++) {
            __half2 h = *(const __half2*)&w[j];
            float2 f = __half22float2(h);
            v[i * 8 + j * 2]     = f.x;
            v[i * 8 + j * 2 + 1] = f.y;
            mx = fmaxf(mx, fmaxf(f.x, f.y));
        }
    }

    __shared__ float red[256];
    red[tid] = mx;
    __syncthreads();
    for (int s = 128; s > 0; s >>= 1) {
        if (tid < s) red[tid] = fmaxf(red[tid], red[tid + s]);
        __syncthreads();
    }
    mx = red[0];
    __syncthreads();

    float sum = 0.0f;
#pragma unroll
    for (int i = 0; i < 32; i++) {
        v[i] = __expf((v[i] - mx) * scale);
        sum += v[i];
    }
    red[tid] = sum;
    __syncthreads();
    for (int s = 128; s > 0; s >>= 1) {
        if (tid < s) red[tid] += red[tid + s];
        __syncthreads();
    }
    const float inv = 1.0f / red[0];

#pragma unroll
    for (int i = 0; i < 4; i++) {
        long idx = row * (long)SEQ + (long)(tid + i * 256) * 8;
        uint4 o;
        o.x = pack_h2(v[i * 8 + 0] * inv, v[i * 8 + 1] * inv);
        o.y = pack_h2(v[i * 8 + 2] * inv, v[i * 8 + 3] * inv);
        o.z = pack_h2(v[i * 8 + 4] * inv, v[i * 8 + 5] * inv);
        o.w = pack_h2(v[i * 8 + 6] * inv, v[i * 8 + 7] * inv);
        *(uint4*)(P + idx) = o;
    }
}

// ======================= launch =======================
extern "C" void kernel_launch(void* const* d_in, const int* in_sizes, int n_in,
                              void* d_out, int out_size)
{
    (void)in_sizes; (void)n_in; (void)out_size;
    const float* X  = (const float*)d_in[0];
    const float* Wq = (const float*)d_in[1];
    const float* Wk = (const float*)d_in[2];
    const float* Wv = (const float*)d_in[3];
    float* O = (float*)d_out;

    __half *X16, *Wq16, *Wk16, *Wv16, *Q16, *K16, *V16, *S16, *P16;
    cudaGetSymbolAddress((void**)&X16, g_X16);
    cudaGetSymbolAddress((void**)&Wq16, g_Wq16);
    cudaGetSymbolAddress((void**)&Wk16, g_Wk16);
    cudaGetSymbolAddress((void**)&Wv16, g_Wv16);
    cudaGetSymbolAddress((void**)&Q16, g_Q16);
    cudaGetSymbolAddress((void**)&K16, g_K16);
    cudaGetSymbolAddress((void**)&V16, g_V16);
    cudaGetSymbolAddress((void**)&S16, g_S16);
    cudaGetSymbolAddress((void**)&P16, g_P16);

    cudaFuncSetAttribute(gemm_nt_h<1>, cudaFuncAttributeMaxDynamicSharedMemorySize, GSMEM_H);
    cudaFuncSetAttribute(gemm_nt_h<0>, cudaFuncAttributeMaxDynamicSharedMemorySize, GSMEM_H);
    cudaFuncSetAttribute(gemm_nn_f16,  cudaFuncAttributeMaxDynamicSharedMemorySize, GSMEM_NN);

    // 1) conversions: everything -> single fp16
    cvt_h1<<<2048, 256>>>(X,  X16,  (long)SEQ * DM / 4);
    cvt_h1<<<1024, 256>>>(Wq, Wq16, (long)DM * DM / 4);
    cvt_h1<<<1024, 256>>>(Wk, Wk16, (long)DM * DM / 4);
    cvt_h1<<<1024, 256>>>(Wv, Wv16, (long)DM * DM / 4);

    dim3 blk(512);
    // 2) projections: Q/K/V = X16 @ W16^T -> fp16  (CTA tile 128x256)
    dim3 gp(DM / 256, SEQ / 128);
    gemm_nt_h<1><<<gp, blk, GSMEM_H>>>(X16, Wq16, nullptr, Q16, DM, DM, DM, DM);
    gemm_nt_h<1><<<gp, blk, GSMEM_H>>>(X16, Wk16, nullptr, K16, DM, DM, DM, DM);
    gemm_nt_h<1><<<gp, blk, GSMEM_H>>>(X16, Wv16, nullptr, V16, DM, DM, DM, DM);

    // 3) S = Q16 @ K16^T -> fp16 (unscaled logits ~N(0,45), well inside fp16 range)
    dim3 gs(SEQ / 256, SEQ / 128);
    gemm_nt_h<1><<<gs, blk, GSMEM_H>>>(Q16, K16, nullptr, S16, DM, DM, DM, SEQ);

    // 4) P = softmax(S * 1/sqrt(DM)) -> fp16
    softmax_f16<<<SEQ, 256>>>(S16, P16);

    // 5) O = P @ V -> fp32  (R12 NN kernel, CTA tile 128x128)
    dim3 go(DM / 128, SEQ / 128);
    gemm_nn_f16<<<go, blk, GSMEM_NN>>>(P16, V16, O, SEQ, SEQ, DM, DM);
}

// round 17
// speedup vs baseline: 1.9480x; 1.0179x over previous
#include <cuda_runtime.h>
#include <cuda_fp16.h>
#include <cstdint>
#include <math.h>

#define SEQ 8192
#define DM  2048
#define DM3 (3 * DM)

// ======================= scratch (device globals) =======================
__device__ __half g_X16[(size_t)SEQ * DM];
__device__ __half g_W3[(size_t)DM3 * DM];       // [Wq; Wk; Wv] stacked rows
__device__ __half g_QKV[(size_t)SEQ * DM3];     // [Q | K | V] slices, ld = DM3
__device__ __half g_S16[(size_t)SEQ * SEQ];
__device__ __half g_P16[(size_t)SEQ * SEQ];

// ======================= helpers =======================
__device__ __forceinline__ uint32_t smem_u32(const void* p) {
    uint32_t a;
    asm("{ .reg .u64 t; cvta.to.shared.u64 t, %1; cvt.u32.u64 %0, t; }" : "=r"(a) : "l"(p));
    return a;
}
#define CP16(sm, gp) \
    asm volatile("cp.async.cg.shared.global [%0], [%1], 16;" :: "r"(sm), "l"(gp))
#define CP_COMMIT() asm volatile("cp.async.commit_group;")
#define CP_WAIT(n)  asm volatile("cp.async.wait_group %0;" :: "n"(n) : "memory")

__device__ __forceinline__ void ldsm_x4(uint32_t* r, uint32_t a) {
    asm volatile("ldmatrix.sync.aligned.m8n8.x4.shared.b16 {%0,%1,%2,%3}, [%4];"
        : "=r"(r[0]), "=r"(r[1]), "=r"(r[2]), "=r"(r[3]) : "r"(a));
}
__device__ __forceinline__ void ldsm_x4_t(uint32_t* r, uint32_t a) {
    asm volatile("ldmatrix.sync.aligned.m8n8.x4.trans.shared.b16 {%0,%1,%2,%3}, [%4];"
        : "=r"(r[0]), "=r"(r[1]), "=r"(r[2]), "=r"(r[3]) : "r"(a));
}
__device__ __forceinline__ void mma16816h(float* c, const uint32_t* a, const uint32_t* b) {
    asm volatile("mma.sync.aligned.m16n8k16.row.col.f32.f16.f16.f32 "
        "{%0,%1,%2,%3}, {%4,%5,%6,%7}, {%8,%9}, {%0,%1,%2,%3};"
        : "+f"(c[0]), "+f"(c[1]), "+f"(c[2]), "+f"(c[3])
        : "r"(a[0]), "r"(a[1]), "r"(a[2]), "r"(a[3]), "r"(b[0]), "r"(b[1]));
}
__device__ __forceinline__ uint32_t pack_h2(float a, float b) {
    __half2 h = __floats2half2_rn(a, b);
    return *(uint32_t*)&h;
}

// ======================= NT GEMM 128x256: C[M,N] = A16[M,K] @ B16[N,K]^T =======================
// 16 warps, warp tile 32x64. 4-stage, 2-ahead prefetch, 1 sync/chunk. fp16 out.
#define STAGE_H (48u * 1024u)
#define GSMEM_H (4 * STAGE_H)
__global__ __launch_bounds__(512, 1)
void gemm_nt_h(const __half* __restrict__ A, const __half* __restrict__ B,
               __half* __restrict__ C16,
               int Kdim, long ldA, long ldB, long ldC)
{
    extern __shared__ char sm[];
    const uint32_t sb = smem_u32(sm);
    const int tid = threadIdx.x, wid = tid >> 5, lane = tid & 31;
    const int wm = wid >> 2, wn = wid & 3;
    const long row0 = (long)blockIdx.y * 128, col0 = (long)blockIdx.x * 256;
    const int NC = Kdim / 64;

    uint32_t soffA[2]; long aoff[2];
#pragma unroll
    for (int j = 0; j < 2; j++) {
        int slot = tid + j * 512;
        int r = slot >> 3, c = slot & 7;
        soffA[j] = (uint32_t)(r * 128 + ((c ^ (r & 7)) << 4));
        aoff[j]  = (row0 + r) * ldA + c * 8;
    }
    uint32_t soffB[4]; long boff[4];
#pragma unroll
    for (int j = 0; j < 4; j++) {
        int slot = tid + j * 512;
        int r = slot >> 3, c = slot & 7;
        soffB[j] = (uint32_t)(16384 + r * 128 + ((c ^ (r & 7)) << 4));
        boff[j]  = (col0 + r) * ldB + c * 8;
    }

    const int g = lane >> 3, lr = lane & 7;
    const int arow_b = wm * 32 + (g & 1) * 8 + lr;
    const int brow_b = wn * 64 + (g & 1) * 8 + lr;
    const int ch_hi = g >> 1;

    float acc[2][8][4];
#pragma unroll
    for (int i = 0; i < 2; i++)
#pragma unroll
        for (int j = 0; j < 8; j++)
#pragma unroll
            for (int q = 0; q < 4; q++) acc[i][j][q] = 0.0f;

#define H_LOAD(buf, kb) do {                                                   \
    uint32_t s_ = sb + (uint32_t)(buf) * STAGE_H;                              \
    _Pragma("unroll")                                                          \
    for (int j = 0; j < 2; j++) CP16(s_ + soffA[j], A + aoff[j] + (kb));       \
    _Pragma("unroll")                                                          \
    for (int j = 0; j < 4; j++) CP16(s_ + soffB[j], B + boff[j] + (kb));       \
    CP_COMMIT();                                                               \
} while (0)

    H_LOAD(0, 0);
    H_LOAD(1, 64);

    for (int i = 0; i < NC; i++) {
        if (i + 2 < NC)      { H_LOAD((i + 2) & 3, (long)(i + 2) * 64); CP_WAIT(2); }
        else if (i + 1 < NC) { CP_WAIT(1); }
        else                 { CP_WAIT(0); }
        __syncthreads();   // single barrier per chunk
        const uint32_t As = sb + (uint32_t)(i & 3) * STAGE_H;
        const uint32_t Bs = As + 16384;

#pragma unroll
        for (int ks = 0; ks < 4; ks++) {
            uint32_t a[2][4], b[8][2];
#pragma unroll
            for (int mf = 0; mf < 2; mf++) {
                int row = arow_b + mf * 16;
                int ch = ks * 2 + ch_hi;
                ldsm_x4(a[mf], As + row * 128 + ((ch ^ (row & 7)) << 4));
            }
#pragma unroll
            for (int np = 0; np < 4; np++) {
                int row = brow_b + np * 16;
                int ch = ks * 2 + ch_hi;
                uint32_t q[4];
                ldsm_x4(q, Bs + row * 128 + ((ch ^ (row & 7)) << 4));
                b[np * 2][0]     = q[0]; b[np * 2][1]     = q[2];
                b[np * 2 + 1][0] = q[1]; b[np * 2 + 1][1] = q[3];
            }
#pragma unroll
            for (int mf = 0; mf < 2; mf++)
#pragma unroll
                for (int nf = 0; nf < 8; nf++)
                    mma16816h(acc[mf][nf], a[mf], b[nf]);
        }
    }

#pragma unroll
    for (int mf = 0; mf < 2; mf++)
#pragma unroll
        for (int nf = 0; nf < 8; nf++) {
            long row = row0 + wm * 32 + mf * 16 + (lane >> 2);
            long col = col0 + wn * 64 + nf * 8 + (lane & 3) * 2;
            *(uint32_t*)(C16 + row * ldC + col)       = pack_h2(acc[mf][nf][0], acc[mf][nf][1]);
            *(uint32_t*)(C16 + (row + 8) * ldC + col) = pack_h2(acc[mf][nf][2], acc[mf][nf][3]);
        }
#undef H_LOAD
}

// ======================= NN GEMM (fp16, 4-stage, 1 sync/chunk): C = A[M,K] @ B[K,N] ==============
// Exact R12/R15 version (128x128 tile).
#define STAGE_NN 32768u
#define GSMEM_NN (4 * STAGE_NN)
__global__ __launch_bounds__(512, 1)
void gemm_nn_f16(const __half* __restrict__ A, const __half* __restrict__ B,
                 float* __restrict__ Cf, int Kdim, long ldA, long ldB, long ldC)
{
    extern __shared__ char sm[];
    const uint32_t sb = smem_u32(sm);
    const int tid = threadIdx.x, wid = tid >> 5, lane = tid & 31;
    const int wm = wid >> 2, wn = wid & 3;
    const long row0 = (long)blockIdx.y * 128, col0 = (long)blockIdx.x * 128;
    const int NC = Kdim / 64;

    uint32_t soffA[2], soffB[2]; long aoff[2], boff[2];
#pragma unroll
    for (int j = 0; j < 2; j++) {
        int slot = tid + j * 512;
        int ra = slot >> 3, ca = slot & 7;
        soffA[j] = (uint32_t)(ra * 128 + ((ca ^ (ra & 7)) << 4));
        aoff[j]  = (row0 + ra) * ldA + ca * 8;
        int rb = slot >> 4, cb = slot & 15;
        soffB[j] = (uint32_t)(rb * 256 + ((cb ^ (rb & 7)) << 4));
        boff[j]  = (long)rb * ldB + col0 + cb * 8;
    }

    const int g = lane >> 3, lr = lane & 7;
    const int arow_b = wm * 32 + (g & 1) * 8 + lr;
    const int krow_b = (g & 1) * 8 + lr;
    const int bch_b  = wn * 4 + (g >> 1);

    float acc[2][4][4];
#pragma unroll
    for (int i = 0; i < 2; i++)
#pragma unroll
        for (int j = 0; j < 4; j++)
#pragma unroll
            for (int q = 0; q < 4; q++) acc[i][j][q] = 0.0f;

#define NN_LOAD(buf, kb) do {                                                  \
    uint32_t s_ = sb + (uint32_t)(buf) * STAGE_NN;                             \
    long kb_ = (kb);                                                           \
    _Pragma("unroll")                                                          \
    for (int j = 0; j < 2; j++) {                                              \
        CP16(s_ +         soffA[j], A + aoff[j] + kb_);                        \
        CP16(s_ + 16384 + soffB[j], B + boff[j] + kb_ * ldB);                  \
    }                                                                          \
    CP_COMMIT();                                                               \
} while (0)

    NN_LOAD(0, 0);
    NN_LOAD(1, 64);

    for (int i = 0; i < NC; i++) {
        if (i + 2 < NC)      { NN_LOAD((i + 2) & 3, (long)(i + 2) * 64); CP_WAIT(2); }
        else if (i + 1 < NC) { CP_WAIT(1); }
        else                 { CP_WAIT(0); }
        __syncthreads();
        const uint32_t As = sb + (uint32_t)(i & 3) * STAGE_NN;
        const uint32_t Bs = As + 16384;

#pragma unroll
        for (int ks = 0; ks < 4; ks++) {
            uint32_t a[2][4], b[4][2];
#pragma unroll
            for (int mf = 0; mf < 2; mf++) {
                int row = arow_b + mf * 16;
                int ch = ks * 2 + (g >> 1);
                ldsm_x4(a[mf], As + row * 128 + ((ch ^ (row & 7)) << 4));
            }
#pragma unroll
            for (int np = 0; np < 2; np++) {
                int krow = krow_b + ks * 16;
                int ch = bch_b + np * 2;
                uint32_t q[4];
                ldsm_x4_t(q, Bs + krow * 256 + ((ch ^ (krow & 7)) << 4));
                b[np * 2][0]     = q[0]; b[np * 2][1]     = q[1];
                b[np * 2 + 1][0] = q[2]; b[np * 2 + 1][1] = q[3];
            }
#pragma unroll
            for (int mf = 0; mf < 2; mf++)
#pragma unroll
                for (int nf = 0; nf < 4; nf++)
                    mma16816h(acc[mf][nf], a[mf], b[nf]);
        }
    }

#pragma unroll
    for (int mf = 0; mf < 2; mf++)
#pragma unroll
        for (int nf = 0; nf < 4; nf++) {
            long row = row0 + wm * 32 + mf * 16 + (lane >> 2);
            long col = col0 + wn * 32 + nf * 8 + (lane & 3) * 2;
            *(float2*)(Cf + row * ldC + col)       = make_float2(acc[mf][nf][0], acc[mf][nf][1]);
            *(float2*)(Cf + (row + 8) * ldC + col) = make_float2(acc[mf][nf][2], acc[mf][nf][3]);
        }
#undef NN_LOAD
}

// ======================= fp32 -> fp16 conversion =======================
__global__ __launch_bounds__(256)
void cvt_h1(const float* __restrict__ s, __half* __restrict__ d, long n4)
{
    for (long i = blockIdx.x * 256 + threadIdx.x; i < n4; i += (long)gridDim.x * 256) {
        float4 v = ((const float4*)s)[i];
        ((uint2*)d)[i] = make_uint2(pack_h2(v.x, v.y), pack_h2(v.z, v.w));
    }
}

// ======================= row softmax: S16 (fp16 logits, pre-scale) -> P16 =======================
__global__ __launch_bounds__(256)
void softmax_f16(const __half* __restrict__ S, __half* __restrict__ P)
{
    const long row = blockIdx.x;
    const uint4* rp = (const uint4*)(S + row * (long)SEQ);  // 8 halves per uint4
    const int tid = threadIdx.x;
    const float scale = 0.02209708691207961f;  // 1/sqrt(2048)

    float v[32];
    float mx = -INFINITY;
#pragma unroll
    for (int i = 0; i < 4; i++) {
        uint4 u = rp[tid + i * 256];
        const uint32_t w[4] = {u.x, u.y, u.z, u.w};
#pragma unroll
        for (int j = 0; j < 4; j++) {
            __half2 h = *(const __half2*)&w[j];
            float2 f = __half22float2(h);
            v[i * 8 + j * 2]     = f.x;
            v[i * 8 + j * 2 + 1] = f.y;
            mx = fmaxf(mx, fmaxf(f.x, f.y));
        }
    }

    __shared__ float red[256];
    red[tid] = mx;
    __syncthreads();
    for (int s = 128; s > 0; s >>= 1) {
        if (tid < s) red[tid] = fmaxf(red[tid], red[tid + s]);
        __syncthreads();
    }
    mx = red[0];
    __syncthreads();

    float sum = 0.0f;
#pragma unroll
    for (int i = 0; i < 32; i++) {
        v[i] = __expf((v[i] - mx) * scale);
        sum += v[i];
    }
    red[tid] = sum;
    __syncthreads();
    for (int s = 128; s > 0; s >>= 1) {
        if (tid < s) red[tid] += red[tid + s];
        __syncthreads();
    }
    const float inv = 1.0f / red[0];

#pragma unroll
    for (int i = 0; i < 4; i++) {
        long idx = row * (long)SEQ + (long)(tid + i * 256) * 8;
        uint4 o;
        o.x = pack_h2(v[i * 8 + 0] * inv, v[i * 8 + 1] * inv);
        o.y = pack_h2(v[i * 8 + 2] * inv, v[i * 8 + 3] * inv);
        o.z = pack_h2(v[i * 8 + 4] * inv, v[i * 8 + 5] * inv);
        o.w = pack_h2(v[i * 8 + 6] * inv, v[i * 8 + 7] * inv);
        *(uint4*)(P + idx) = o;
    }
}

// ======================= launch =======================
extern "C" void kernel_launch(void* const* d_in, const int* in_sizes, int n_in,
                              void* d_out, int out_size)
{
    (void)in_sizes; (void)n_in; (void)out_size;
    const float* X  = (const float*)d_in[0];
    const float* Wq = (const float*)d_in[1];
    const float* Wk = (const float*)d_in[2];
    const float* Wv = (const float*)d_in[3];
    float* O = (float*)d_out;

    __half *X16, *W3, *QKV, *S16, *P16;
    cudaGetSymbolAddress((void**)&X16, g_X16);
    cudaGetSymbolAddress((void**)&W3,  g_W3);
    cudaGetSymbolAddress((void**)&QKV, g_QKV);
    cudaGetSymbolAddress((void**)&S16, g_S16);
    cudaGetSymbolAddress((void**)&P16, g_P16);

    cudaFuncSetAttribute(gemm_nt_h,   cudaFuncAttributeMaxDynamicSharedMemorySize, GSMEM_H);
    cudaFuncSetAttribute(gemm_nn_f16, cudaFuncAttributeMaxDynamicSharedMemorySize, GSMEM_NN);

    // 1) conversions: X -> fp16; Wq/Wk/Wv -> stacked W3 [3*DM, DM] fp16
    const long WN4 = (long)DM * DM / 4;
    cvt_h1<<<2048, 256>>>(X,  X16, (long)SEQ * DM / 4);
    cvt_h1<<<1024, 256>>>(Wq, W3,                       WN4);
    cvt_h1<<<1024, 256>>>(Wk, W3 + (size_t)DM * DM,     WN4);
    cvt_h1<<<1024, 256>>>(Wv, W3 + (size_t)2 * DM * DM, WN4);

    dim3 blk(512);
    // 2) fused QKV projection: QKV[SEQ, 3*DM] = X16 @ W3^T  (one launch, CTA tile 128x256)
    dim3 gp(DM3 / 256, SEQ / 128);
    gemm_nt_h<<<gp, blk, GSMEM_H>>>(X16, W3, QKV, DM, DM, DM, DM3);

    __half* Q16 = QKV;            // ld = DM3
    __half* K16 = QKV + DM;       // ld = DM3
    __half* V16 = QKV + 2 * DM;   // ld = DM3

    // 3) S = Q16 @ K16^T -> fp16 (unscaled logits ~N(0,45), well inside fp16 range)
    dim3 gs(SEQ / 256, SEQ / 128);
    gemm_nt_h<<<gs, blk, GSMEM_H>>>(Q16, K16, S16, DM, DM3, DM3, SEQ);

    // 4) P = softmax(S * 1/sqrt(DM)) -> fp16
    softmax_f16<<<SEQ, 256>>>(S16, P16);

    // 5) O = P @ V -> fp32  (R15 NN kernel, V strided ld=DM3)
    dim3 go(DM / 128, SEQ / 128);
    gemm_nn_f16<<<go, blk, GSMEM_NN>>>(P16, V16, O, SEQ, SEQ, DM3, DM);
}